// round 5
// baseline (speedup 1.0000x reference)
#include <cuda_runtime.h>

#define Nn   5000
#define Bb   16
#define BD   512   // B*DIN

__device__ float g_P[(size_t)Nn * Nn];
__device__ float g_rowmax[Nn];
__device__ float g_rowsum[Nn];
__device__ float g_xT[Nn * BD];
__device__ float g_y1[Nn * BD];
__device__ float g_y2[Nn * BD];
__device__ float g_Wg[(size_t)Nn * 3072];
__device__ float g_ww[(size_t)Nn * 512];
__device__ float g_xwagg[Nn * Bb * 16];

__global__ void reset_kernel() {
    int i = blockIdx.x * 256 + threadIdx.x;
    if (i < Nn) g_rowmax[i] = 0.0f;
}

// P = relu(E E^T); row-max via atomics
__global__ void logits_kernel(const float* __restrict__ emb) {
    __shared__ float Ea[64][65];
    __shared__ float EbT[64][68];
    __shared__ unsigned rmaxs[64];
    int tx = threadIdx.x, ty = threadIdx.y;
    int tid = ty * 16 + tx;
    int m0 = blockIdx.y * 64, n0 = blockIdx.x * 64;
    if (tid < 64) rmaxs[tid] = 0u;
    #pragma unroll
    for (int q = 0; q < 16; q++) {
        int fid = tid + 256 * q;
        int row = fid >> 6, d = fid & 63;
        Ea[row][d]  = (m0 + row < Nn) ? emb[(m0 + row) * 64 + d] : 0.0f;
        EbT[d][row] = (n0 + row < Nn) ? emb[(n0 + row) * 64 + d] : 0.0f;
    }
    __syncthreads();
    float acc[4][4];
    #pragma unroll
    for (int r = 0; r < 4; r++)
        #pragma unroll
        for (int c = 0; c < 4; c++) acc[r][c] = 0.0f;
    #pragma unroll 4
    for (int d = 0; d < 64; d++) {
        float af[4];
        #pragma unroll
        for (int r = 0; r < 4; r++) af[r] = Ea[ty * 4 + r][d];
        float4 bv = *(const float4*)&EbT[d][tx * 4];
        float bf[4] = {bv.x, bv.y, bv.z, bv.w};
        #pragma unroll
        for (int r = 0; r < 4; r++)
            #pragma unroll
            for (int c = 0; c < 4; c++)
                acc[r][c] = fmaf(af[r], bf[c], acc[r][c]);
    }
    #pragma unroll
    for (int r = 0; r < 4; r++) {
        unsigned rm = 0u;
        #pragma unroll
        for (int c = 0; c < 4; c++) {
            acc[r][c] = fmaxf(acc[r][c], 0.0f);
            rm = max(rm, __float_as_uint(acc[r][c]));
        }
        atomicMax(&rmaxs[ty * 4 + r], rm);
        int m = m0 + ty * 4 + r;
        if (m < Nn && n0 + tx * 4 + 4 <= Nn) {
            float4 v = {acc[r][0], acc[r][1], acc[r][2], acc[r][3]};
            *(float4*)&g_P[(size_t)m * Nn + n0 + tx * 4] = v;
        }
    }
    __syncthreads();
    if (tid < 64 && m0 + tid < Nn)
        atomicMax((unsigned*)&g_rowmax[m0 + tid], rmaxs[tid]);
}

// P = exp(P - rowmax); rowsum (one block per row)
__global__ void exp_kernel() {
    int row = blockIdx.x;
    float rmax = g_rowmax[row];
    float s = 0.0f;
    for (int col = threadIdx.x; col < Nn; col += 256) {
        size_t idx = (size_t)row * Nn + col;
        float e = __expf(g_P[idx] - rmax);
        g_P[idx] = e;
        s += e;
    }
    __shared__ float red[256];
    red[threadIdx.x] = s;
    __syncthreads();
    for (int o = 128; o > 0; o >>= 1) {
        if (threadIdx.x < o) red[threadIdx.x] += red[threadIdx.x + o];
        __syncthreads();
    }
    if (threadIdx.x == 0) g_rowsum[row] = red[0];
}

// x [B,N,32] -> xT [N][b*32+c]
__global__ void transpose_x(const float* __restrict__ x) {
    int idx = blockIdx.x * 256 + threadIdx.x;
    if (idx >= Nn * BD) return;
    int m = idx >> 9, r = idx & 511, b = r >> 5, c = r & 31;
    g_xT[idx] = x[((size_t)b * Nn + m) * 32 + c];
}

// xwagg[n][b*16+i] = sum_t T[t]*x_window[b,t,n,i]
__global__ void xwagg_kernel(const float* __restrict__ xw, const float* __restrict__ T) {
    int idx = blockIdx.x * 256 + threadIdx.x;
    if (idx >= Nn * Bb * 16) return;
    int n = idx >> 8, r = idx & 255, b = r >> 4, i = r & 15;
    float s = 0.0f;
    #pragma unroll
    for (int t = 0; t < 12; t++)
        s = fmaf(__ldg(&T[t]), xw[(((size_t)b * 12 + t) * Nn + n) * 16 + i], s);
    g_xwagg[idx] = s;
}

// out[n][j] = sum_d emb[n,d]*pool[d,j]   (which 0 -> g_Wg J=3072, 1 -> g_ww J=512)
__global__ void __launch_bounds__(128) pool_gemm(const float* __restrict__ emb,
                                                 const float* __restrict__ pool,
                                                 int J, int which) {
    float* out = (which == 0) ? g_Wg : g_ww;
    __shared__ float embT[64][36];
    int tid = threadIdx.x;
    int n0 = blockIdx.y * 32;
    #pragma unroll
    for (int q = 0; q < 16; q++) {
        int fid = tid + 128 * q;
        int r = fid >> 6, d = fid & 63;
        embT[d][r] = (n0 + r < Nn) ? emb[(n0 + r) * 64 + d] : 0.0f;
    }
    __syncthreads();
    int tx = tid & 31, ty = tid >> 5;
    int j0 = blockIdx.x * 128 + tx * 4;
    int r0 = ty * 8;
    float acc[8][4];
    #pragma unroll
    for (int i = 0; i < 8; i++)
        #pragma unroll
        for (int j = 0; j < 4; j++) acc[i][j] = 0.0f;
    #pragma unroll 4
    for (int d = 0; d < 64; d++) {
        float4 pv = *(const float4*)&pool[(size_t)d * J + j0];
        float pf[4] = {pv.x, pv.y, pv.z, pv.w};
        float4 e0 = *(const float4*)&embT[d][r0];
        float4 e1 = *(const float4*)&embT[d][r0 + 4];
        float af[8] = {e0.x, e0.y, e0.z, e0.w, e1.x, e1.y, e1.z, e1.w};
        #pragma unroll
        for (int i = 0; i < 8; i++)
            #pragma unroll
            for (int j = 0; j < 4; j++)
                acc[i][j] = fmaf(af[i], pf[j], acc[i][j]);
    }
    #pragma unroll
    for (int i = 0; i < 8; i++) {
        int n = n0 + r0 + i;
        if (n < Nn) {
            float4 v = {acc[i][0], acc[i][1], acc[i][2], acc[i][3]};
            *(float4*)&out[(size_t)n * J + j0] = v;
        }
    }
}

// C = diag(1/rowsum) * (P @ B),  M=K=5000, Ncols=512. 128x64 tile, 128 thr, dbl-buf
#define GEMM_LOAD(t) do {                                                        \
    int k0 = (t) * 16;                                                           \
    _Pragma("unroll")                                                            \
    for (int q = 0; q < 4; q++) {                                                \
        int kk = k0 + q * 4;                                                     \
        areg[q] = (aok && kk < Nn) ? *(const float4*)(Ap + kk)                   \
                                   : make_float4(0.f, 0.f, 0.f, 0.f);            \
    }                                                                            \
    breg[0] = (k0 + brow0 < Nn)                                                  \
        ? *(const float4*)(Bm + (size_t)(k0 + brow0) * BD + j0 + bc0)            \
        : make_float4(0.f, 0.f, 0.f, 0.f);                                       \
    breg[1] = (k0 + brow1 < Nn)                                                  \
        ? *(const float4*)(Bm + (size_t)(k0 + brow1) * BD + j0 + bc1)            \
        : make_float4(0.f, 0.f, 0.f, 0.f);                                       \
} while (0)

#define GEMM_STS(buf) do {                                                       \
    _Pragma("unroll")                                                            \
    for (int q = 0; q < 4; q++) {                                                \
        As[buf][4 * q + 0][tid] = areg[q].x;                                     \
        As[buf][4 * q + 1][tid] = areg[q].y;                                     \
        As[buf][4 * q + 2][tid] = areg[q].z;                                     \
        As[buf][4 * q + 3][tid] = areg[q].w;                                     \
    }                                                                            \
    *(float4*)&Bs[buf][brow0][bc0] = breg[0];                                    \
    *(float4*)&Bs[buf][brow1][bc1] = breg[1];                                    \
} while (0)

__global__ void __launch_bounds__(128, 2) big_gemm(int which) {
    const float* __restrict__ A  = g_P;
    const float* __restrict__ Bm = which ? g_y1 : g_xT;
    float* __restrict__ C        = which ? g_y2 : g_y1;

    __shared__ float As[2][16][128];
    __shared__ float Bs[2][16][64];

    int tid = threadIdx.x;
    int ty = tid >> 3, tx = tid & 7;
    int m0 = blockIdx.y * 128, j0 = blockIdx.x * 64;

    int arow = m0 + tid;
    bool aok = arow < Nn;
    const float* Ap = A + (size_t)(aok ? arow : 0) * Nn;

    int brow0 = tid >> 4,         bc0 = (tid & 15) * 4;
    int brow1 = (tid + 128) >> 4, bc1 = bc0;

    float4 areg[4], breg[2];
    float acc[8][8];
    #pragma unroll
    for (int i = 0; i < 8; i++)
        #pragma unroll
        for (int j = 0; j < 8; j++) acc[i][j] = 0.0f;

    const int nk = (Nn + 15) >> 4;
    GEMM_LOAD(0);
    GEMM_STS(0);
    __syncthreads();

    for (int t = 0; t < nk; ++t) {
        int buf = t & 1;
        bool more = (t + 1 < nk);
        if (more) GEMM_LOAD(t + 1);
        #pragma unroll
        for (int kk = 0; kk < 16; kk++) {
            float4 a0 = *(const float4*)&As[buf][kk][ty * 8];
            float4 a1 = *(const float4*)&As[buf][kk][ty * 8 + 4];
            float4 b0 = *(const float4*)&Bs[buf][kk][tx * 8];
            float4 b1 = *(const float4*)&Bs[buf][kk][tx * 8 + 4];
            float a[8] = {a0.x, a0.y, a0.z, a0.w, a1.x, a1.y, a1.z, a1.w};
            float b[8] = {b0.x, b0.y, b0.z, b0.w, b1.x, b1.y, b1.z, b1.w};
            #pragma unroll
            for (int i = 0; i < 8; i++)
                #pragma unroll
                for (int j = 0; j < 8; j++)
                    acc[i][j] = fmaf(a[i], b[j], acc[i][j]);
        }
        if (more) GEMM_STS(buf ^ 1);
        __syncthreads();
    }

    #pragma unroll
    for (int r = 0; r < 8; r++) {
        int m = m0 + ty * 8 + r;
        if (m >= Nn) continue;
        float alpha = 1.0f / g_rowsum[m];
        float4 v0 = {acc[r][0] * alpha, acc[r][1] * alpha, acc[r][2] * alpha, acc[r][3] * alpha};
        float4 v1 = {acc[r][4] * alpha, acc[r][5] * alpha, acc[r][6] * alpha, acc[r][7] * alpha};
        *(float4*)&C[(size_t)m * BD + j0 + tx * 8]     = v0;
        *(float4*)&C[(size_t)m * BD + j0 + tx * 8 + 4] = v1;
    }
}

// fused: gconv + wconv + LN + bias + concat. one block per node.
__global__ void __launch_bounds__(128) final_kernel(const float* __restrict__ x,
                                                    const float* __restrict__ emb,
                                                    const float* __restrict__ bpool,
                                                    const float* __restrict__ ln1w,
                                                    const float* __restrict__ ln1b,
                                                    const float* __restrict__ ln2w,
                                                    const float* __restrict__ ln2b,
                                                    float* __restrict__ out) {
    int n = blockIdx.x;
    int tid = threadIdx.x;
    __shared__ float sW[3072];
    __shared__ float sww[512];
    __shared__ float sx[3][512];
    __shared__ float sxa[256];
    __shared__ float sg[512];
    __shared__ float sw2[512];
    __shared__ float semb[64];
    __shared__ float sbias[64];
    __shared__ float smu[16], srs[16], smu2[16], srs2[16];

    #pragma unroll
    for (int q = 0; q < 6; q++) {
        int f = tid + 128 * q;
        *(float4*)&sW[f * 4] = *(const float4*)&g_Wg[(size_t)n * 3072 + f * 4];
    }
    *(float4*)&sww[tid * 4] = *(const float4*)&g_ww[(size_t)n * 512 + tid * 4];
    {
        int b = tid >> 3, i4 = (tid & 7) * 4;
        *(float4*)&sx[0][tid * 4] = *(const float4*)&x[((size_t)b * Nn + n) * 32 + i4];
    }
    *(float4*)&sx[1][tid * 4] = *(const float4*)&g_y1[(size_t)n * BD + tid * 4];
    *(float4*)&sx[2][tid * 4] = *(const float4*)&g_y2[(size_t)n * BD + tid * 4];
    if (tid < 64) {
        *(float4*)&sxa[tid * 4] = *(const float4*)&g_xwagg[(size_t)n * 256 + tid * 4];
        semb[tid] = emb[(size_t)n * 64 + tid];
    }
    __syncthreads();

    #pragma unroll
    for (int q = 0; q < 4; q++) {
        int s = tid + 128 * q;
        int b = s >> 5, o = s & 31;
        float a = 0.0f;
        #pragma unroll
        for (int k = 0; k < 3; k++)
            #pragma unroll
            for (int i = 0; i < 32; i++)
                a = fmaf(sx[k][b * 32 + i], sW[k * 1024 + i * 32 + o], a);
        sg[s] = a;
        float w = 0.0f;
        #pragma unroll
        for (int i = 0; i < 16; i++)
            w = fmaf(sxa[b * 16 + i], sww[i * 32 + o], w);
        sw2[s] = w;
    }
    if (tid < 64) {
        float bsum = 0.0f;
        #pragma unroll
        for (int d = 0; d < 64; d++)
            bsum = fmaf(semb[d], __ldg(&bpool[d * 64 + tid]), bsum);
        sbias[tid] = bsum;
    }
    __syncthreads();

    if (tid < 16) {
        float s1 = 0, q1 = 0, s2 = 0, q2 = 0;
        #pragma unroll
        for (int o = 0; o < 32; o++) {
            float v = sg[tid * 32 + o];
            s1 += v; q1 = fmaf(v, v, q1);
            float u = sw2[tid * 32 + o];
            s2 += u; q2 = fmaf(u, u, q2);
        }
        float mu1 = s1 * (1.0f / 32.0f), mu2 = s2 * (1.0f / 32.0f);
        smu[tid] = mu1;
        srs[tid] = rsqrtf(fmaxf(q1 * (1.0f / 32.0f) - mu1 * mu1, 0.0f) + 1e-5f);
        smu2[tid] = mu2;
        srs2[tid] = rsqrtf(fmaxf(q2 * (1.0f / 32.0f) - mu2 * mu2, 0.0f) + 1e-5f);
    }
    __syncthreads();

    #pragma unroll
    for (int q = 0; q < 8; q++) {
        int s = tid + 128 * q;
        int b = s >> 6, h = s & 63;
        float v;
        if (h < 32)
            v = (sg[b * 32 + h] - smu[b]) * srs[b] * __ldg(&ln1w[h]) + __ldg(&ln1b[h]);
        else
            v = (sw2[b * 32 + h - 32] - smu2[b]) * srs2[b] * __ldg(&ln2w[h - 32]) + __ldg(&ln2b[h - 32]);
        out[((size_t)b * Nn + n) * 64 + h] = v + sbias[h];
    }
}

extern "C" void kernel_launch(void* const* d_in, const int* in_sizes, int n_in,
                              void* d_out, int out_size) {
    const float* x    = (const float*)d_in[0];
    const float* xw   = (const float*)d_in[1];
    const float* emb  = (const float*)d_in[2];
    const float* wp   = (const float*)d_in[3];
    const float* wwin = (const float*)d_in[4];
    const float* bp   = (const float*)d_in[5];
    const float* T    = (const float*)d_in[6];
    const float* l1w  = (const float*)d_in[7];
    const float* l1b  = (const float*)d_in[8];
    const float* l2w  = (const float*)d_in[9];
    const float* l2b  = (const float*)d_in[10];
    float* out = (float*)d_out;

    reset_kernel<<<20, 256>>>();
    logits_kernel<<<dim3(79, 79), dim3(16, 16)>>>(emb);
    exp_kernel<<<Nn, 256>>>();
    transpose_x<<<(Nn * BD + 255) / 256, 256>>>(x);
    xwagg_kernel<<<(Nn * Bb * 16 + 255) / 256, 256>>>(xw, T);
    pool_gemm<<<dim3(24, 157), 128>>>(emb, wp, 3072, 0);
    pool_gemm<<<dim3(4, 157), 128>>>(emb, wwin, 512, 1);
    big_gemm<<<dim3(8, 40), 128>>>(0);
    big_gemm<<<dim3(8, 40), 128>>>(1);
    final_kernel<<<Nn, 128>>>(x, emb, bp, l1w, l1b, l2w, l2b, out);
}

// round 7
// speedup vs baseline: 2.6395x; 2.6395x over previous
#include <cuda_runtime.h>
#include <cuda_bf16.h>
#include <cstdint>

#define Nn   5000
#define Bb   16
#define MP   5120          // padded node dim (K and M), 80*64 = 40*128
#define NK   80            // MP/64 k-chunks

// ---------------- scratch (device globals, zero-initialized at load) ----------------
__device__ float g_P[(size_t)Nn * Nn];
__device__ float g_rowmax[Nn];
__device__ float g_rowsum[Nn];
__device__ __nv_bfloat16 g_Phi[(size_t)MP * MP];
__device__ __nv_bfloat16 g_Plo[(size_t)MP * MP];
__device__ __nv_bfloat16 g_xT_hi[(size_t)512 * MP];
__device__ __nv_bfloat16 g_xT_lo[(size_t)512 * MP];
__device__ __nv_bfloat16 g_y1T_hi[(size_t)512 * MP];
__device__ __nv_bfloat16 g_y1T_lo[(size_t)512 * MP];
__device__ float g_y1[(size_t)Nn * 512];
__device__ float g_y2[(size_t)Nn * 512];
__device__ float g_Wg[(size_t)Nn * 3072];
__device__ float g_ww[(size_t)Nn * 512];
__device__ float g_xwagg[Nn * Bb * 16];

// ---------------- base-ISA tensor helpers (no 'a'-target features) ----------------
__device__ __forceinline__ void cpa16(uint32_t s, const void* g) {
    asm volatile("cp.async.cg.shared.global [%0], [%1], 16;" :: "r"(s), "l"(g) : "memory");
}
__device__ __forceinline__ void ldsm4(uint32_t* r, uint32_t a) {
    asm volatile("ldmatrix.sync.aligned.m8n8.x4.shared.b16 {%0,%1,%2,%3}, [%4];"
                 : "=r"(r[0]), "=r"(r[1]), "=r"(r[2]), "=r"(r[3]) : "r"(a));
}
__device__ __forceinline__ void ldsm2(uint32_t* r, uint32_t a) {
    asm volatile("ldmatrix.sync.aligned.m8n8.x2.shared.b16 {%0,%1}, [%2];"
                 : "=r"(r[0]), "=r"(r[1]) : "r"(a));
}
__device__ __forceinline__ void mma16816(float* d, const uint32_t* a, const uint32_t* b) {
    asm volatile("mma.sync.aligned.m16n8k16.row.col.f32.bf16.bf16.f32 "
                 "{%0,%1,%2,%3}, {%4,%5,%6,%7}, {%8,%9}, {%0,%1,%2,%3};"
                 : "+f"(d[0]), "+f"(d[1]), "+f"(d[2]), "+f"(d[3])
                 : "r"(a[0]), "r"(a[1]), "r"(a[2]), "r"(a[3]), "r"(b[0]), "r"(b[1]));
}

// ---------------- small kernels ----------------
__global__ void reset_kernel() {
    int i = blockIdx.x * 256 + threadIdx.x;
    if (i < Nn) g_rowmax[i] = 0.0f;
}

// P = relu(E E^T) fp32; row-max via atomics
__global__ void logits_kernel(const float* __restrict__ emb) {
    __shared__ float Ea[64][65];
    __shared__ float EbT[64][68];
    __shared__ unsigned rmaxs[64];
    int tx = threadIdx.x, ty = threadIdx.y;
    int tid = ty * 16 + tx;
    int m0 = blockIdx.y * 64, n0 = blockIdx.x * 64;
    if (tid < 64) rmaxs[tid] = 0u;
    #pragma unroll
    for (int q = 0; q < 16; q++) {
        int fid = tid + 256 * q;
        int row = fid >> 6, d = fid & 63;
        Ea[row][d]  = (m0 + row < Nn) ? emb[(m0 + row) * 64 + d] : 0.0f;
        EbT[d][row] = (n0 + row < Nn) ? emb[(n0 + row) * 64 + d] : 0.0f;
    }
    __syncthreads();
    float acc[4][4];
    #pragma unroll
    for (int r = 0; r < 4; r++)
        #pragma unroll
        for (int c = 0; c < 4; c++) acc[r][c] = 0.0f;
    #pragma unroll 4
    for (int d = 0; d < 64; d++) {
        float af[4];
        #pragma unroll
        for (int r = 0; r < 4; r++) af[r] = Ea[ty * 4 + r][d];
        float4 bv = *(const float4*)&EbT[d][tx * 4];
        float bf[4] = {bv.x, bv.y, bv.z, bv.w};
        #pragma unroll
        for (int r = 0; r < 4; r++)
            #pragma unroll
            for (int c = 0; c < 4; c++)
                acc[r][c] = fmaf(af[r], bf[c], acc[r][c]);
    }
    #pragma unroll
    for (int r = 0; r < 4; r++) {
        unsigned rm = 0u;
        #pragma unroll
        for (int c = 0; c < 4; c++) {
            acc[r][c] = fmaxf(acc[r][c], 0.0f);
            rm = max(rm, __float_as_uint(acc[r][c]));
        }
        atomicMax(&rmaxs[ty * 4 + r], rm);
        int m = m0 + ty * 4 + r;
        if (m < Nn && n0 + tx * 4 + 4 <= Nn) {
            float4 v = {acc[r][0], acc[r][1], acc[r][2], acc[r][3]};
            *(float4*)&g_P[(size_t)m * Nn + n0 + tx * 4] = v;
        }
    }
    __syncthreads();
    if (tid < 64 && m0 + tid < Nn)
        atomicMax((unsigned*)&g_rowmax[m0 + tid], rmaxs[tid]);
}

// exp + rowsum; writes P as bf16 hi/lo into padded [MP x MP] layout
__global__ void exp_kernel() {
    int row = blockIdx.x;
    float rmax = g_rowmax[row];
    float s = 0.0f;
    for (int col = threadIdx.x; col < Nn; col += 256) {
        float e = __expf(g_P[(size_t)row * Nn + col] - rmax);
        __nv_bfloat16 hi = __float2bfloat16(e);
        g_Phi[(size_t)row * MP + col] = hi;
        g_Plo[(size_t)row * MP + col] = __float2bfloat16(e - __bfloat162float(hi));
        s += e;
    }
    __shared__ float red[256];
    red[threadIdx.x] = s;
    __syncthreads();
    for (int o = 128; o > 0; o >>= 1) {
        if (threadIdx.x < o) red[threadIdx.x] += red[threadIdx.x + o];
        __syncthreads();
    }
    if (threadIdx.x == 0) g_rowsum[row] = red[0];
}

// x [B,N,32] -> x^T hi/lo [j=b*32+c][m] stride MP
__global__ void transpose_x(const float* __restrict__ x) {
    __shared__ float t[64][65];
    int m0 = blockIdx.x * 64, j0 = blockIdx.y * 64;
    #pragma unroll
    for (int q = 0; q < 16; q++) {
        int f = threadIdx.x + 256 * q;
        int mr = f >> 6, jj = f & 63;
        int m = m0 + mr, j = j0 + jj;
        float v = (m < Nn) ? x[(((size_t)(j >> 5)) * Nn + m) * 32 + (j & 31)] : 0.0f;
        t[jj][mr] = v;
    }
    __syncthreads();
    #pragma unroll
    for (int q = 0; q < 16; q++) {
        int f = threadIdx.x + 256 * q;
        int jj = f >> 6, mr = f & 63;
        int m = m0 + mr;
        if (m < Nn) {
            float v = t[jj][mr];
            __nv_bfloat16 hi = __float2bfloat16(v);
            g_xT_hi[(size_t)(j0 + jj) * MP + m] = hi;
            g_xT_lo[(size_t)(j0 + jj) * MP + m] = __float2bfloat16(v - __bfloat162float(hi));
        }
    }
}

// xwagg[n][b*16+i] = sum_t T[t]*x_window[b,t,n,i]
__global__ void xwagg_kernel(const float* __restrict__ xw, const float* __restrict__ T) {
    int idx = blockIdx.x * 256 + threadIdx.x;
    if (idx >= Nn * Bb * 16) return;
    int n = idx >> 8, r = idx & 255, b = r >> 4, i = r & 15;
    float s = 0.0f;
    #pragma unroll
    for (int t = 0; t < 12; t++)
        s = fmaf(__ldg(&T[t]), xw[(((size_t)b * 12 + t) * Nn + n) * 16 + i], s);
    g_xwagg[idx] = s;
}

// out[n][j] = sum_d emb[n,d]*pool[d,j]
__global__ void __launch_bounds__(128) pool_gemm(const float* __restrict__ emb,
                                                 const float* __restrict__ pool,
                                                 int J, int which) {
    float* out = (which == 0) ? g_Wg : g_ww;
    __shared__ float embT[64][36];
    int tid = threadIdx.x;
    int n0 = blockIdx.y * 32;
    #pragma unroll
    for (int q = 0; q < 16; q++) {
        int fid = tid + 128 * q;
        int r = fid >> 6, d = fid & 63;
        embT[d][r] = (n0 + r < Nn) ? emb[(n0 + r) * 64 + d] : 0.0f;
    }
    __syncthreads();
    int tx = tid & 31, ty = tid >> 5;
    int j0 = blockIdx.x * 128 + tx * 4;
    int r0 = ty * 8;
    float acc[8][4];
    #pragma unroll
    for (int i = 0; i < 8; i++)
        #pragma unroll
        for (int j = 0; j < 4; j++) acc[i][j] = 0.0f;
    #pragma unroll 4
    for (int d = 0; d < 64; d++) {
        float4 pv = *(const float4*)&pool[(size_t)d * J + j0];
        float pf[4] = {pv.x, pv.y, pv.z, pv.w};
        float4 e0 = *(const float4*)&embT[d][r0];
        float4 e1 = *(const float4*)&embT[d][r0 + 4];
        float af[8] = {e0.x, e0.y, e0.z, e0.w, e1.x, e1.y, e1.z, e1.w};
        #pragma unroll
        for (int i = 0; i < 8; i++)
            #pragma unroll
            for (int j = 0; j < 4; j++)
                acc[i][j] = fmaf(af[i], pf[j], acc[i][j]);
    }
    #pragma unroll
    for (int i = 0; i < 8; i++) {
        int n = n0 + r0 + i;
        if (n < Nn) {
            float4 v = {acc[i][0], acc[i][1], acc[i][2], acc[i][3]};
            *(float4*)&out[(size_t)n * J + j0] = v;
        }
    }
}

// ---------------- HMMA GEMM: C = diag(1/rowsum)*(P @ Bt^T) ----------------
// CTA tile 160(m) x 128(j), K-chunk 64, 8 warps (2m x 4n), warp tile 80x32.
// 3 bf16 passes (hi*hi + hi*lo + lo*hi) into shared fp32 reg accumulators.
#define MT 160
#define JT 128
#define ABYTES 20480            // 160 rows * 128B (one A tile, hi or lo)
#define BBYTES 16384            // 128 rows * 128B
#define BUFB   (2 * ABYTES + 2 * BBYTES)   // 73728
#define SMEM_BYTES (1024 + 2 * BUFB)
#define SST 132                 // epilogue staging stride (floats)

__global__ void __launch_bounds__(256) tc_gemm(int which) {
    extern __shared__ char dsm[];
    uint32_t raw;
    asm("{ .reg .u64 t; cvta.to.shared.u64 t, %1; cvt.u32.u64 %0, t; }" : "=r"(raw) : "l"(dsm));
    uint32_t sb = (raw + 1023u) & ~1023u;

    int tid = threadIdx.x, lane = tid & 31, wid = tid >> 5;
    int wm = wid >> 2, wn = wid & 3;              // 2 x 4 warp grid
    int m0 = blockIdx.y * MT, j0 = blockIdx.x * JT;

    const __nv_bfloat16* __restrict__ BThi = which ? g_y1T_hi : g_xT_hi;
    const __nv_bfloat16* __restrict__ BTlo = which ? g_y1T_lo : g_xT_lo;

    // cp.async staging: A 5 units/thread (160*8), B 4 units/thread (128*8)
    uint32_t sA[5], sB[4];
    size_t gA[5], gB[4];
    #pragma unroll
    for (int q = 0; q < 5; q++) {
        int u = tid + 256 * q;
        int row = u >> 3, c16 = u & 7;
        sA[q] = (uint32_t)(row * 128 + ((c16 ^ (row & 7)) * 16));
        gA[q] = (size_t)(m0 + row) * MP + c16 * 8;
    }
    #pragma unroll
    for (int q = 0; q < 4; q++) {
        int u = tid + 256 * q;
        int row = u >> 3, c16 = u & 7;
        sB[q] = (uint32_t)(row * 128 + ((c16 ^ (row & 7)) * 16));
        gB[q] = (size_t)(j0 + row) * MP + c16 * 8;
    }

    auto issue = [&](int t) {
        uint32_t base = sb + (uint32_t)(t & 1) * BUFB;
        size_t ko = (size_t)t * 64;
        #pragma unroll
        for (int q = 0; q < 5; q++) cpa16(base + sA[q], g_Phi + gA[q] + ko);
        #pragma unroll
        for (int q = 0; q < 5; q++) cpa16(base + ABYTES + sA[q], g_Plo + gA[q] + ko);
        #pragma unroll
        for (int q = 0; q < 4; q++) cpa16(base + 2 * ABYTES + sB[q], BThi + gB[q] + ko);
        #pragma unroll
        for (int q = 0; q < 4; q++) cpa16(base + 2 * ABYTES + BBYTES + sB[q], BTlo + gB[q] + ko);
        asm volatile("cp.async.commit_group;" ::: "memory");
    };

    // ldmatrix geometry
    uint32_t a_off[5], a7[5], b_off[4], b7[4];
    int hb = lane >> 4;            // A: k half (0/1)
    int bb = (lane >> 3) & 1;      // B: k half
    #pragma unroll
    for (int mf = 0; mf < 5; mf++) {
        int arow = wm * 80 + mf * 16 + (lane & 15);
        a_off[mf] = (uint32_t)(arow * 128);
        a7[mf] = (uint32_t)(arow & 7);
    }
    #pragma unroll
    for (int nf = 0; nf < 4; nf++) {
        int brow = wn * 32 + nf * 8 + (lane & 7);
        b_off[nf] = (uint32_t)(brow * 128);
        b7[nf] = (uint32_t)(brow & 7);
    }

    float acc[5][4][4];
    #pragma unroll
    for (int mf = 0; mf < 5; mf++)
        #pragma unroll
        for (int nf = 0; nf < 4; nf++)
            #pragma unroll
            for (int e = 0; e < 4; e++) acc[mf][nf][e] = 0.0f;

    issue(0);
    for (int t = 0; t < NK; t++) {
        if (t + 1 < NK) {
            issue(t + 1);
            asm volatile("cp.async.wait_group 1;" ::: "memory");
        } else {
            asm volatile("cp.async.wait_group 0;" ::: "memory");
        }
        __syncthreads();

        uint32_t Ah = sb + (uint32_t)(t & 1) * BUFB;
        uint32_t Al = Ah + ABYTES;
        uint32_t Bh = Ah + 2 * ABYTES;
        uint32_t Bl = Bh + BBYTES;

        #pragma unroll
        for (int ks = 0; ks < 4; ks++) {
            uint32_t ahf[5][4], alf[5][4], bhf[4][2], blf[4][2];
            uint32_t ca = (uint32_t)(ks * 2 + hb);
            uint32_t cb = (uint32_t)(ks * 2 + bb);
            #pragma unroll
            for (int mf = 0; mf < 5; mf++) {
                uint32_t x = a_off[mf] + ((ca ^ a7[mf]) << 4);
                ldsm4(ahf[mf], Ah + x);
                ldsm4(alf[mf], Al + x);
            }
            #pragma unroll
            for (int nf = 0; nf < 4; nf++) {
                uint32_t x = b_off[nf] + ((cb ^ b7[nf]) << 4);
                ldsm2(bhf[nf], Bh + x);
                ldsm2(blf[nf], Bl + x);
            }
            #pragma unroll
            for (int mf = 0; mf < 5; mf++)
                #pragma unroll
                for (int nf = 0; nf < 4; nf++) {
                    mma16816(acc[mf][nf], ahf[mf], bhf[nf]);
                    mma16816(acc[mf][nf], ahf[mf], blf[nf]);
                    mma16816(acc[mf][nf], alf[mf], bhf[nf]);
                }
        }
        __syncthreads();
    }

    // ---- epilogue: scale by 1/rowsum, stage in smem, write Y (+ y1T hi/lo) ----
    float* st = (float*)(dsm + (sb - raw));
    int g = lane >> 2, tig = lane & 3;
    #pragma unroll
    for (int mf = 0; mf < 5; mf++) {
        int r0 = wm * 80 + mf * 16 + g;
        int ma = m0 + r0, mb = ma + 8;
        float al0 = (ma < Nn) ? __frcp_rn(g_rowsum[ma]) : 0.0f;
        float al1 = (mb < Nn) ? __frcp_rn(g_rowsum[mb]) : 0.0f;
        #pragma unroll
        for (int nf = 0; nf < 4; nf++) {
            int c0 = wn * 32 + nf * 8 + tig * 2;
            st[r0 * SST + c0]           = acc[mf][nf][0] * al0;
            st[r0 * SST + c0 + 1]       = acc[mf][nf][1] * al0;
            st[(r0 + 8) * SST + c0]     = acc[mf][nf][2] * al1;
            st[(r0 + 8) * SST + c0 + 1] = acc[mf][nf][3] * al1;
        }
    }
    __syncthreads();

    float* __restrict__ Y = which ? g_y2 : g_y1;
    for (int u = tid; u < MT * 32; u += 256) {
        int r = u >> 5, ch = u & 31;
        int m = m0 + r;
        if (m < Nn) {
            float4 v = {st[r * SST + ch * 4],     st[r * SST + ch * 4 + 1],
                        st[r * SST + ch * 4 + 2], st[r * SST + ch * 4 + 3]};
            *(float4*)&Y[(size_t)m * 512 + j0 + ch * 4] = v;
        }
    }
    if (which == 0) {
        for (int u = tid; u < JT * 20; u += 256) {
            int j = u / 20, mm = u % 20;
            uint32_t wh[4], wl[4];
            #pragma unroll
            for (int p = 0; p < 4; p++) {
                float v0 = st[(mm * 8 + 2 * p) * SST + j];
                float v1 = st[(mm * 8 + 2 * p + 1) * SST + j];
                __nv_bfloat16 h0 = __float2bfloat16(v0);
                __nv_bfloat16 h1 = __float2bfloat16(v1);
                __nv_bfloat16 l0 = __float2bfloat16(v0 - __bfloat162float(h0));
                __nv_bfloat16 l1 = __float2bfloat16(v1 - __bfloat162float(h1));
                wh[p] = (uint32_t)__bfloat16_as_ushort(h0) | ((uint32_t)__bfloat16_as_ushort(h1) << 16);
                wl[p] = (uint32_t)__bfloat16_as_ushort(l0) | ((uint32_t)__bfloat16_as_ushort(l1) << 16);
            }
            size_t off = (size_t)(j0 + j) * MP + m0 + mm * 8;
            *(uint4*)&g_y1T_hi[off] = make_uint4(wh[0], wh[1], wh[2], wh[3]);
            *(uint4*)&g_y1T_lo[off] = make_uint4(wl[0], wl[1], wl[2], wl[3]);
        }
    }
}

// ---------------- fused epilogue: gconv + wconv + LN + bias + concat ----------------
__global__ void __launch_bounds__(128) final_kernel(const float* __restrict__ x,
                                                    const float* __restrict__ emb,
                                                    const float* __restrict__ bpool,
                                                    const float* __restrict__ ln1w,
                                                    const float* __restrict__ ln1b,
                                                    const float* __restrict__ ln2w,
                                                    const float* __restrict__ ln2b,
                                                    float* __restrict__ out) {
    int n = blockIdx.x;
    int tid = threadIdx.x;
    __shared__ float sW[3072];
    __shared__ float sww[512];
    __shared__ float sx[3][512];
    __shared__ float sxa[256];
    __shared__ float sg[512];
    __shared__ float sw2[512];
    __shared__ float semb[64];
    __shared__ float sbias[64];
    __shared__ float smu[16], srs[16], smu2[16], srs2[16];

    #pragma unroll
    for (int q = 0; q < 6; q++) {
        int f = tid + 128 * q;
        *(float4*)&sW[f * 4] = *(const float4*)&g_Wg[(size_t)n * 3072 + f * 4];
    }
    *(float4*)&sww[tid * 4] = *(const float4*)&g_ww[(size_t)n * 512 + tid * 4];
    {
        int b = tid >> 3, i4 = (tid & 7) * 4;
        *(float4*)&sx[0][tid * 4] = *(const float4*)&x[((size_t)b * Nn + n) * 32 + i4];
    }
    *(float4*)&sx[1][tid * 4] = *(const float4*)&g_y1[(size_t)n * 512 + tid * 4];
    *(float4*)&sx[2][tid * 4] = *(const float4*)&g_y2[(size_t)n * 512 + tid * 4];
    if (tid < 64) {
        *(float4*)&sxa[tid * 4] = *(const float4*)&g_xwagg[(size_t)n * 256 + tid * 4];
        semb[tid] = emb[(size_t)n * 64 + tid];
    }
    __syncthreads();

    #pragma unroll
    for (int q = 0; q < 4; q++) {
        int s = tid + 128 * q;
        int b = s >> 5, o = s & 31;
        float a = 0.0f;
        #pragma unroll
        for (int k = 0; k < 3; k++)
            #pragma unroll
            for (int i = 0; i < 32; i++)
                a = fmaf(sx[k][b * 32 + i], sW[k * 1024 + i * 32 + o], a);
        sg[s] = a;
        float w = 0.0f;
        #pragma unroll
        for (int i = 0; i < 16; i++)
            w = fmaf(sxa[b * 16 + i], sww[i * 32 + o], w);
        sw2[s] = w;
    }
    if (tid < 64) {
        float bsum = 0.0f;
        #pragma unroll
        for (int d = 0; d < 64; d++)
            bsum = fmaf(semb[d], __ldg(&bpool[d * 64 + tid]), bsum);
        sbias[tid] = bsum;
    }
    __syncthreads();

    if (tid < 16) {
        float s1 = 0, q1 = 0, s2 = 0, q2 = 0;
        #pragma unroll
        for (int o = 0; o < 32; o++) {
            float v = sg[tid * 32 + o];
            s1 += v; q1 = fmaf(v, v, q1);
            float u = sw2[tid * 32 + o];
            s2 += u; q2 = fmaf(u, u, q2);
        }
        float mu1 = s1 * (1.0f / 32.0f), mu2 = s2 * (1.0f / 32.0f);
        smu[tid] = mu1;
        srs[tid] = rsqrtf(fmaxf(q1 * (1.0f / 32.0f) - mu1 * mu1, 0.0f) + 1e-5f);
        smu2[tid] = mu2;
        srs2[tid] = rsqrtf(fmaxf(q2 * (1.0f / 32.0f) - mu2 * mu2, 0.0f) + 1e-5f);
    }
    __syncthreads();

    #pragma unroll
    for (int q = 0; q < 8; q++) {
        int s = tid + 128 * q;
        int b = s >> 6, h = s & 63;
        float v;
        if (h < 32)
            v = (sg[b * 32 + h] - smu[b]) * srs[b] * __ldg(&ln1w[h]) + __ldg(&ln1b[h]);
        else
            v = (sw2[b * 32 + h - 32] - smu2[b]) * srs2[b] * __ldg(&ln2w[h - 32]) + __ldg(&ln2b[h - 32]);
        out[((size_t)b * Nn + n) * 64 + h] = v + sbias[h];
    }
}

extern "C" void kernel_launch(void* const* d_in, const int* in_sizes, int n_in,
                              void* d_out, int out_size) {
    const float* x    = (const float*)d_in[0];
    const float* xw   = (const float*)d_in[1];
    const float* emb  = (const float*)d_in[2];
    const float* wp   = (const float*)d_in[3];
    const float* wwin = (const float*)d_in[4];
    const float* bp   = (const float*)d_in[5];
    const float* T    = (const float*)d_in[6];
    const float* l1w  = (const float*)d_in[7];
    const float* l1b  = (const float*)d_in[8];
    const float* l2w  = (const float*)d_in[9];
    const float* l2b  = (const float*)d_in[10];
    float* out = (float*)d_out;

    cudaFuncSetAttribute(tc_gemm, cudaFuncAttributeMaxDynamicSharedMemorySize, SMEM_BYTES);

    reset_kernel<<<20, 256>>>();
    logits_kernel<<<dim3(79, 79), dim3(16, 16)>>>(emb);
    exp_kernel<<<Nn, 256>>>();
    transpose_x<<<dim3(79, 8), 256>>>(x);
    xwagg_kernel<<<(Nn * Bb * 16 + 255) / 256, 256>>>(xw, T);
    pool_gemm<<<dim3(24, 157), 128>>>(emb, wp, 3072, 0);
    pool_gemm<<<dim3(4, 157), 128>>>(emb, wwin, 512, 1);
    tc_gemm<<<dim3(4, 32), 256, SMEM_BYTES>>>(0);
    tc_gemm<<<dim3(4, 32), 256, SMEM_BYTES>>>(1);
    final_kernel<<<Nn, 128>>>(x, emb, bp, l1w, l1b, l2w, l2b, out);
}

// round 8
// speedup vs baseline: 3.4182x; 1.2950x over previous
#include <cuda_runtime.h>
#include <cuda_fp16.h>
#include <cstdint>

#define Nn   5000
#define Bb   16
#define MP   5120          // padded node dim, 40*128 = 32*160
#define NK   80            // MP/64 k-chunks

// ---------------- scratch (device globals, zero-initialized at load) ----------------
__device__ __half g_Eh[(size_t)MP * 64];
__device__ __half g_El[(size_t)MP * 64];
__device__ float g_rowmax[MP];            // atomicMax (idempotent across replays)
__device__ float g_rsp[4][MP];            // rowsum partials per n-chunk
__device__ __half g_Ph[(size_t)MP * MP];  // P hi limb
__device__ __half g_Pl[(size_t)MP * MP];  // P lo limb
__device__ __half g_xT_h[(size_t)512 * MP];
__device__ __half g_y1T_h[(size_t)512 * MP];
__device__ float g_y1[(size_t)Nn * 512];
__device__ float g_y2[(size_t)Nn * 512];
__device__ float g_Wg[(size_t)Nn * 3072];
__device__ float g_ww[(size_t)Nn * 512];
__device__ float g_xwagg[Nn * Bb * 16];

// ---------------- base-ISA tensor helpers ----------------
__device__ __forceinline__ void cpa16(uint32_t s, const void* g) {
    asm volatile("cp.async.cg.shared.global [%0], [%1], 16;" :: "r"(s), "l"(g) : "memory");
}
__device__ __forceinline__ void ldsm4(uint32_t* r, uint32_t a) {
    asm volatile("ldmatrix.sync.aligned.m8n8.x4.shared.b16 {%0,%1,%2,%3}, [%4];"
                 : "=r"(r[0]), "=r"(r[1]), "=r"(r[2]), "=r"(r[3]) : "r"(a));
}
__device__ __forceinline__ void ldsm2(uint32_t* r, uint32_t a) {
    asm volatile("ldmatrix.sync.aligned.m8n8.x2.shared.b16 {%0,%1}, [%2];"
                 : "=r"(r[0]), "=r"(r[1]) : "r"(a));
}
__device__ __forceinline__ void mma_h(float* d, const uint32_t* a, const uint32_t* b) {
    asm volatile("mma.sync.aligned.m16n8k16.row.col.f32.f16.f16.f32 "
                 "{%0,%1,%2,%3}, {%4,%5,%6,%7}, {%8,%9}, {%0,%1,%2,%3};"
                 : "+f"(d[0]), "+f"(d[1]), "+f"(d[2]), "+f"(d[3])
                 : "r"(a[0]), "r"(a[1]), "r"(a[2]), "r"(a[3]), "r"(b[0]), "r"(b[1]));
}
__device__ __forceinline__ uint32_t pack2h(float a, float b) {
    __half2 h = __halves2half2(__float2half_rn(a), __float2half_rn(b));
    return *(uint32_t*)&h;
}
__device__ __forceinline__ uint32_t smem_u32(const void* p) {
    uint32_t r;
    asm("{ .reg .u64 t; cvta.to.shared.u64 t, %1; cvt.u32.u64 %0, t; }" : "=r"(r) : "l"(p));
    return r;
}

// ---------------- prep: x transpose (fp16) + emb hi/lo limbs ----------------
__global__ void prep_kernel(const float* __restrict__ x, const float* __restrict__ emb) {
    __shared__ float t[64][65];
    if (blockIdx.x < 632) {
        int mt = blockIdx.x % 79, jt = blockIdx.x / 79;
        int m0 = mt * 64, j0 = jt * 64;
        #pragma unroll
        for (int q = 0; q < 16; q++) {
            int f = threadIdx.x + 256 * q;
            int mr = f >> 6, jj = f & 63;
            int m = m0 + mr, j = j0 + jj;
            float v = (m < Nn) ? x[(((size_t)(j >> 5)) * Nn + m) * 32 + (j & 31)] : 0.0f;
            t[jj][mr] = v;
        }
        __syncthreads();
        #pragma unroll
        for (int q = 0; q < 16; q++) {
            int f = threadIdx.x + 256 * q;
            int jj = f >> 6, mr = f & 63;
            int m = m0 + mr;
            if (m < Nn)
                g_xT_h[(size_t)(j0 + jj) * MP + m] = __float2half_rn(t[jj][mr]);
        }
    } else {
        int gid = (blockIdx.x - 632) * 256 + threadIdx.x;
        for (int i = gid; i < Nn * 64; i += 20 * 256) {
            float v = emb[i];
            __half h = __float2half_rn(v);
            g_Eh[i] = h;
            g_El[i] = __float2half_rn(v - __half2float(h));
        }
    }
}

// ---------------- rowmax: 1-pass fp16 relu(E E^T) row max ----------------
__global__ void __launch_bounds__(256) rowmax_tc() {
    __shared__ __align__(16) char sm[33280];
    uint32_t raw = smem_u32(sm);
    uint32_t SAH = raw, SBH = raw + 16384;
    unsigned* smax = (unsigned*)(sm + 32768);
    int tid = threadIdx.x, lane = tid & 31, wid = tid >> 5;
    int wm = wid >> 2, wn = wid & 3;
    int m0 = blockIdx.y * 128, nb = blockIdx.x * 2560;

    #pragma unroll
    for (int q = 0; q < 4; q++) {
        int u = tid + 256 * q;
        int row = u >> 3, c16 = u & 7;
        uint4 v = *(const uint4*)(g_Eh + (size_t)(m0 + row) * 64 + c16 * 8);
        *(uint4*)(sm + (row * 128 + ((c16 ^ (row & 7)) * 16))) = v;
    }
    if (tid < 128) smax[tid] = 0u;
    __syncthreads();

    int hb = lane >> 4, bb = (lane >> 3) & 1;
    uint32_t a_off[4], a7[4], b_off[4], b7[4];
    #pragma unroll
    for (int mf = 0; mf < 4; mf++) {
        int ar = wm * 64 + mf * 16 + (lane & 15);
        a_off[mf] = (uint32_t)(ar * 128); a7[mf] = (uint32_t)(ar & 7);
    }
    #pragma unroll
    for (int nf = 0; nf < 4; nf++) {
        int br = wn * 32 + nf * 8 + (lane & 7);
        b_off[nf] = (uint32_t)(br * 128); b7[nf] = (uint32_t)(br & 7);
    }

    float rmx[4][2];
    #pragma unroll
    for (int mf = 0; mf < 4; mf++) { rmx[mf][0] = 0.0f; rmx[mf][1] = 0.0f; }

    for (int sub = 0; sub < 20; sub++) {
        int n0 = nb + sub * 128;
        #pragma unroll
        for (int q = 0; q < 4; q++) {
            int u = tid + 256 * q;
            int row = u >> 3, c16 = u & 7;
            uint4 v = *(const uint4*)(g_Eh + (size_t)(n0 + row) * 64 + c16 * 8);
            *(uint4*)(sm + 16384 + (row * 128 + ((c16 ^ (row & 7)) * 16))) = v;
        }
        __syncthreads();
        float acc[4][4][4];
        #pragma unroll
        for (int mf = 0; mf < 4; mf++)
            #pragma unroll
            for (int nf = 0; nf < 4; nf++)
                #pragma unroll
                for (int e = 0; e < 4; e++) acc[mf][nf][e] = 0.0f;
        #pragma unroll
        for (int ks = 0; ks < 4; ks++) {
            uint32_t af[4][4], bf[4][2];
            uint32_t ca = (uint32_t)(ks * 2 + hb), cb = (uint32_t)(ks * 2 + bb);
            #pragma unroll
            for (int mf = 0; mf < 4; mf++) ldsm4(af[mf], SAH + a_off[mf] + ((ca ^ a7[mf]) << 4));
            #pragma unroll
            for (int nf = 0; nf < 4; nf++) ldsm2(bf[nf], SBH + b_off[nf] + ((cb ^ b7[nf]) << 4));
            #pragma unroll
            for (int mf = 0; mf < 4; mf++)
                #pragma unroll
                for (int nf = 0; nf < 4; nf++) mma_h(acc[mf][nf], af[mf], bf[nf]);
        }
        #pragma unroll
        for (int mf = 0; mf < 4; mf++)
            #pragma unroll
            for (int nf = 0; nf < 4; nf++) {
                rmx[mf][0] = fmaxf(rmx[mf][0], fmaxf(acc[mf][nf][0], acc[mf][nf][1]));
                rmx[mf][1] = fmaxf(rmx[mf][1], fmaxf(acc[mf][nf][2], acc[mf][nf][3]));
            }
        __syncthreads();
    }
    int g = lane >> 2;
    #pragma unroll
    for (int mf = 0; mf < 4; mf++) {
        int r1 = wm * 64 + mf * 16 + g;
        atomicMax(&smax[r1], __float_as_uint(rmx[mf][0]));
        atomicMax(&smax[r1 + 8], __float_as_uint(rmx[mf][1]));
    }
    __syncthreads();
    if (tid < 128) atomicMax((unsigned*)&g_rowmax[m0 + tid], smax[tid]);
}

// ---------------- pexp: 3-pass fp16 logits + relu + exp + P limbs + rowsum ----------------
#define PE_SMEM 101376
__global__ void __launch_bounds__(256) pexp_tc() {
    extern __shared__ char sm[];
    uint32_t raw = smem_u32(sm);
    uint32_t SAH = raw, SAL = raw + 16384, SBH = raw + 32768, SBL = raw + 49152;
    float* stg   = (float*)(sm + 32768);     // overlaps B tiles (phased)
    float* rsum  = (float*)(sm + 100352);
    float* rmaxS = (float*)(sm + 100864);

    int tid = threadIdx.x, lane = tid & 31, wid = tid >> 5;
    int wm = wid >> 2, wn = wid & 3;
    int m0 = blockIdx.y * 128, nc0 = blockIdx.x * 1280;

    #pragma unroll
    for (int q = 0; q < 8; q++) {
        int id = tid + 256 * q;
        int half = id >> 10, u = id & 1023;
        int row = u >> 3, c16 = u & 7;
        const __half* src = half ? g_El : g_Eh;
        uint4 v = *(const uint4*)(src + (size_t)(m0 + row) * 64 + c16 * 8);
        *(uint4*)(sm + (half ? 16384 : 0) + row * 128 + ((c16 ^ (row & 7)) * 16)) = v;
    }
    if (tid < 128) { rsum[tid] = 0.0f; rmaxS[tid] = g_rowmax[m0 + tid]; }
    __syncthreads();

    int hb = lane >> 4, bb = (lane >> 3) & 1;
    uint32_t a_off[4], a7[4], b_off[4], b7[4];
    #pragma unroll
    for (int mf = 0; mf < 4; mf++) {
        int ar = wm * 64 + mf * 16 + (lane & 15);
        a_off[mf] = (uint32_t)(ar * 128); a7[mf] = (uint32_t)(ar & 7);
    }
    #pragma unroll
    for (int nf = 0; nf < 4; nf++) {
        int br = wn * 32 + nf * 8 + (lane & 7);
        b_off[nf] = (uint32_t)(br * 128); b7[nf] = (uint32_t)(br & 7);
    }

    for (int sub = 0; sub < 10; sub++) {
        int n0 = nc0 + sub * 128;
        #pragma unroll
        for (int q = 0; q < 8; q++) {
            int id = tid + 256 * q;
            int half = id >> 10, u = id & 1023;
            int row = u >> 3, c16 = u & 7;
            const __half* src = half ? g_El : g_Eh;
            uint4 v = *(const uint4*)(src + (size_t)(n0 + row) * 64 + c16 * 8);
            *(uint4*)(sm + (half ? 49152 : 32768) + row * 128 + ((c16 ^ (row & 7)) * 16)) = v;
        }
        __syncthreads();

        float acc[4][4][4];
        #pragma unroll
        for (int mf = 0; mf < 4; mf++)
            #pragma unroll
            for (int nf = 0; nf < 4; nf++)
                #pragma unroll
                for (int e = 0; e < 4; e++) acc[mf][nf][e] = 0.0f;
        #pragma unroll
        for (int ks = 0; ks < 4; ks++) {
            uint32_t ah[4][4], al[4][4], bh[4][2], bl[4][2];
            uint32_t ca = (uint32_t)(ks * 2 + hb), cb = (uint32_t)(ks * 2 + bb);
            #pragma unroll
            for (int mf = 0; mf < 4; mf++) {
                uint32_t xo = a_off[mf] + ((ca ^ a7[mf]) << 4);
                ldsm4(ah[mf], SAH + xo);
                ldsm4(al[mf], SAL + xo);
            }
            #pragma unroll
            for (int nf = 0; nf < 4; nf++) {
                uint32_t xo = b_off[nf] + ((cb ^ b7[nf]) << 4);
                ldsm2(bh[nf], SBH + xo);
                ldsm2(bl[nf], SBL + xo);
            }
            #pragma unroll
            for (int mf = 0; mf < 4; mf++)
                #pragma unroll
                for (int nf = 0; nf < 4; nf++) {
                    mma_h(acc[mf][nf], ah[mf], bh[nf]);
                    mma_h(acc[mf][nf], ah[mf], bl[nf]);
                    mma_h(acc[mf][nf], al[mf], bh[nf]);
                }
        }
        __syncthreads();   // mma done before staging overwrites B region

        int g = lane >> 2, t4 = lane & 3;
        #pragma unroll
        for (int mf = 0; mf < 4; mf++) {
            int r1 = wm * 64 + mf * 16 + g, r2 = r1 + 8;
            float mx1 = rmaxS[r1], mx2 = rmaxS[r2];
            #pragma unroll
            for (int nf = 0; nf < 4; nf++) {
                int c = wn * 32 + nf * 8 + t4 * 2;
                stg[r1 * 132 + c]     = __expf(fmaxf(acc[mf][nf][0], 0.0f) - mx1);
                stg[r1 * 132 + c + 1] = __expf(fmaxf(acc[mf][nf][1], 0.0f) - mx1);
                stg[r2 * 132 + c]     = __expf(fmaxf(acc[mf][nf][2], 0.0f) - mx2);
                stg[r2 * 132 + c + 1] = __expf(fmaxf(acc[mf][nf][3], 0.0f) - mx2);
            }
        }
        __syncthreads();

        if (tid < 128) {
            float s = 0.0f;
            #pragma unroll 8
            for (int c = 0; c < 128; c++) s += stg[tid * 132 + c];
            rsum[tid] += s;
        }
        #pragma unroll
        for (int q = 0; q < 8; q++) {
            int id = tid + 256 * q;
            int row = id >> 4, cu = id & 15;
            uint32_t wh[4], wl[4];
            #pragma unroll
            for (int p = 0; p < 4; p++) {
                float f0 = stg[row * 132 + cu * 8 + 2 * p];
                float f1 = stg[row * 132 + cu * 8 + 2 * p + 1];
                __half h0 = __float2half_rn(f0), h1 = __float2half_rn(f1);
                float l0 = f0 - __half2float(h0), l1 = f1 - __half2float(h1);
                wh[p] = pack2h(__half2float(h0), __half2float(h1));
                wl[p] = pack2h(l0, l1);
            }
            size_t off = (size_t)(m0 + row) * MP + n0 + cu * 8;
            *(uint4*)(g_Ph + off) = make_uint4(wh[0], wh[1], wh[2], wh[3]);
            *(uint4*)(g_Pl + off) = make_uint4(wl[0], wl[1], wl[2], wl[3]);
        }
        __syncthreads();   // staging consumed before next B load
    }
    if (tid < 128) g_rsp[blockIdx.x][m0 + tid] = rsum[tid];
}

// ---------------- HMMA GEMM: C = diag(1/rowsum)*(P @ Bt^T), fp16 2-pass ----------------
#define MT 160
#define JT 128
#define ABYTES 20480
#define BBYTES 16384
#define BUFB   (2 * ABYTES + BBYTES)      // 57344
#define SMEM_BYTES (1024 + 2 * BUFB)      // 115712
#define SST 132

__global__ void __launch_bounds__(256) tc_gemm(int which) {
    extern __shared__ char dsm[];
    uint32_t raw = smem_u32(dsm);
    uint32_t sb = (raw + 1023u) & ~1023u;

    int tid = threadIdx.x, lane = tid & 31, wid = tid >> 5;
    int wm = wid >> 2, wn = wid & 3;
    int m0 = blockIdx.y * MT, j0 = blockIdx.x * JT;

    const __half* __restrict__ BT = which ? g_y1T_h : g_xT_h;

    uint32_t sA[5], sB[4];
    size_t gA[5], gB[4];
    #pragma unroll
    for (int q = 0; q < 5; q++) {
        int u = tid + 256 * q;
        int row = u >> 3, c16 = u & 7;
        sA[q] = (uint32_t)(row * 128 + ((c16 ^ (row & 7)) * 16));
        gA[q] = (size_t)(m0 + row) * MP + c16 * 8;
    }
    #pragma unroll
    for (int q = 0; q < 4; q++) {
        int u = tid + 256 * q;
        int row = u >> 3, c16 = u & 7;
        sB[q] = (uint32_t)(row * 128 + ((c16 ^ (row & 7)) * 16));
        gB[q] = (size_t)(j0 + row) * MP + c16 * 8;
    }

    auto issue = [&](int t) {
        uint32_t base = sb + (uint32_t)(t & 1) * BUFB;
        size_t ko = (size_t)t * 64;
        #pragma unroll
        for (int q = 0; q < 5; q++) cpa16(base + sA[q], g_Ph + gA[q] + ko);
        #pragma unroll
        for (int q = 0; q < 5; q++) cpa16(base + ABYTES + sA[q], g_Pl + gA[q] + ko);
        #pragma unroll
        for (int q = 0; q < 4; q++) cpa16(base + 2 * ABYTES + sB[q], BT + gB[q] + ko);
        asm volatile("cp.async.commit_group;" ::: "memory");
    };

    uint32_t a_off[5], a7[5], b_off[4], b7[4];
    int hb = lane >> 4, bb = (lane >> 3) & 1;
    #pragma unroll
    for (int mf = 0; mf < 5; mf++) {
        int ar = wm * 80 + mf * 16 + (lane & 15);
        a_off[mf] = (uint32_t)(ar * 128); a7[mf] = (uint32_t)(ar & 7);
    }
    #pragma unroll
    for (int nf = 0; nf < 4; nf++) {
        int br = wn * 32 + nf * 8 + (lane & 7);
        b_off[nf] = (uint32_t)(br * 128); b7[nf] = (uint32_t)(br & 7);
    }

    float acc[5][4][4];
    #pragma unroll
    for (int mf = 0; mf < 5; mf++)
        #pragma unroll
        for (int nf = 0; nf < 4; nf++)
            #pragma unroll
            for (int e = 0; e < 4; e++) acc[mf][nf][e] = 0.0f;

    issue(0);
    for (int t = 0; t < NK; t++) {
        if (t + 1 < NK) {
            issue(t + 1);
            asm volatile("cp.async.wait_group 1;" ::: "memory");
        } else {
            asm volatile("cp.async.wait_group 0;" ::: "memory");
        }
        __syncthreads();

        uint32_t Ah = sb + (uint32_t)(t & 1) * BUFB;
        uint32_t Al = Ah + ABYTES;
        uint32_t Bh = Ah + 2 * ABYTES;

        #pragma unroll
        for (int ks = 0; ks < 4; ks++) {
            uint32_t ahf[5][4], alf[5][4], bhf[4][2];
            uint32_t ca = (uint32_t)(ks * 2 + hb), cb = (uint32_t)(ks * 2 + bb);
            #pragma unroll
            for (int mf = 0; mf < 5; mf++) {
                uint32_t xo = a_off[mf] + ((ca ^ a7[mf]) << 4);
                ldsm4(ahf[mf], Ah + xo);
                ldsm4(alf[mf], Al + xo);
            }
            #pragma unroll
            for (int nf = 0; nf < 4; nf++) {
                uint32_t xo = b_off[nf] + ((cb ^ b7[nf]) << 4);
                ldsm2(bhf[nf], Bh + xo);
            }
            #pragma unroll
            for (int mf = 0; mf < 5; mf++)
                #pragma unroll
                for (int nf = 0; nf < 4; nf++) {
                    mma_h(acc[mf][nf], ahf[mf], bhf[nf]);
                    mma_h(acc[mf][nf], alf[mf], bhf[nf]);
                }
        }
        __syncthreads();
    }

    // epilogue: alpha = 1/rowsum (from 4 partials, fixed order), stage, write
    float* st = (float*)(dsm + (sb - raw));
    int g = lane >> 2, t4 = lane & 3;
    #pragma unroll
    for (int mf = 0; mf < 5; mf++) {
        int r0 = wm * 80 + mf * 16 + g;
        int ma = m0 + r0, mb = ma + 8;
        float al0 = 0.0f, al1 = 0.0f;
        if (ma < Nn) al0 = 1.0f / (g_rsp[0][ma] + g_rsp[1][ma] + g_rsp[2][ma] + g_rsp[3][ma]);
        if (mb < Nn) al1 = 1.0f / (g_rsp[0][mb] + g_rsp[1][mb] + g_rsp[2][mb] + g_rsp[3][mb]);
        #pragma unroll
        for (int nf = 0; nf < 4; nf++) {
            int c0 = wn * 32 + nf * 8 + t4 * 2;
            st[r0 * SST + c0]           = acc[mf][nf][0] * al0;
            st[r0 * SST + c0 + 1]       = acc[mf][nf][1] * al0;
            st[(r0 + 8) * SST + c0]     = acc[mf][nf][2] * al1;
            st[(r0 + 8) * SST + c0 + 1] = acc[mf][nf][3] * al1;
        }
    }
    __syncthreads();

    float* __restrict__ Y = which ? g_y2 : g_y1;
    for (int u = tid; u < MT * 32; u += 256) {
        int r = u >> 5, ch = u & 31;
        int m = m0 + r;
        if (m < Nn) {
            float4 v = {st[r * SST + ch * 4],     st[r * SST + ch * 4 + 1],
                        st[r * SST + ch * 4 + 2], st[r * SST + ch * 4 + 3]};
            *(float4*)&Y[(size_t)m * 512 + j0 + ch * 4] = v;
        }
    }
    if (which == 0) {
        for (int u = tid; u < JT * 20; u += 256) {
            int j = u / 20, mm = u % 20;
            uint32_t w[4];
            #pragma unroll
            for (int p = 0; p < 4; p++)
                w[p] = pack2h(st[(mm * 8 + 2 * p) * SST + j],
                              st[(mm * 8 + 2 * p + 1) * SST + j]);
            *(uint4*)&g_y1T_h[(size_t)(j0 + j) * MP + m0 + mm * 8] =
                make_uint4(w[0], w[1], w[2], w[3]);
        }
    }
}

// ---------------- xwagg ----------------
__global__ void xwagg_kernel(const float* __restrict__ xw, const float* __restrict__ T) {
    int idx = blockIdx.x * 256 + threadIdx.x;
    if (idx >= Nn * Bb * 16) return;
    int n = idx >> 8, r = idx & 255, b = r >> 4, i = r & 15;
    float s = 0.0f;
    #pragma unroll
    for (int t = 0; t < 12; t++)
        s = fmaf(__ldg(&T[t]), xw[(((size_t)b * 12 + t) * Nn + n) * 16 + i], s);
    g_xwagg[idx] = s;
}

// ---------------- pool gemm (FFMA) ----------------
__global__ void __launch_bounds__(128) pool_gemm(const float* __restrict__ emb,
                                                 const float* __restrict__ pool,
                                                 int J, int which) {
    float* out = (which == 0) ? g_Wg : g_ww;
    __shared__ float embT[64][36];
    int tid = threadIdx.x;
    int n0 = blockIdx.y * 32;
    #pragma unroll
    for (int q = 0; q < 16; q++) {
        int fid = tid + 128 * q;
        int r = fid >> 6, d = fid & 63;
        embT[d][r] = (n0 + r < Nn) ? emb[(n0 + r) * 64 + d] : 0.0f;
    }
    __syncthreads();
    int tx = tid & 31, ty = tid >> 5;
    int j0 = blockIdx.x * 128 + tx * 4;
    int r0 = ty * 8;
    float acc[8][4];
    #pragma unroll
    for (int i = 0; i < 8; i++)
        #pragma unroll
        for (int j = 0; j < 4; j++) acc[i][j] = 0.0f;
    #pragma unroll 4
    for (int d = 0; d < 64; d++) {
        float4 pv = *(const float4*)&pool[(size_t)d * J + j0];
        float pf[4] = {pv.x, pv.y, pv.z, pv.w};
        float4 e0 = *(const float4*)&embT[d][r0];
        float4 e1 = *(const float4*)&embT[d][r0 + 4];
        float af[8] = {e0.x, e0.y, e0.z, e0.w, e1.x, e1.y, e1.z, e1.w};
        #pragma unroll
        for (int i = 0; i < 8; i++)
            #pragma unroll
            for (int j = 0; j < 4; j++)
                acc[i][j] = fmaf(af[i], pf[j], acc[i][j]);
    }
    #pragma unroll
    for (int i = 0; i < 8; i++) {
        int n = n0 + r0 + i;
        if (n < Nn) {
            float4 v = {acc[i][0], acc[i][1], acc[i][2], acc[i][3]};
            *(float4*)&out[(size_t)n * J + j0] = v;
        }
    }
}

// ---------------- fused epilogue ----------------
__global__ void __launch_bounds__(128) final_kernel(const float* __restrict__ x,
                                                    const float* __restrict__ emb,
                                                    const float* __restrict__ bpool,
                                                    const float* __restrict__ ln1w,
                                                    const float* __restrict__ ln1b,
                                                    const float* __restrict__ ln2w,
                                                    const float* __restrict__ ln2b,
                                                    float* __restrict__ out) {
    int n = blockIdx.x;
    int tid = threadIdx.x;
    __shared__ float sW[3072];
    __shared__ float sww[512];
    __shared__ float sx[3][512];
    __shared__ float sxa[256];
    __shared__ float sg[512];
    __shared__ float sw2[512];
    __shared__ float semb[64];
    __shared__ float sbias[64];
    __shared__ float smu[16], srs[16], smu2[16], srs2[16];

    #pragma unroll
    for (int q = 0; q < 6; q++) {
        int f = tid + 128 * q;
        *(float4*)&sW[f * 4] = *(const float4*)&g_Wg[(size_t)n * 3072 + f * 4];
    }
    *(float4*)&sww[tid * 4] = *(const float4*)&g_ww[(size_t)n * 512 + tid * 4];
    {
        int b = tid >> 3, i4 = (tid & 7) * 4;
        *(float4*)&sx[0][tid * 4] = *(const float4*)&x[((size_t)b * Nn + n) * 32 + i4];
    }
    *(float4*)&sx[1][tid * 4] = *(const float4*)&g_y1[(size_t)n * 512 + tid * 4];
    *(float4*)&sx[2][tid * 4] = *(const float4*)&g_y2[(size_t)n * 512 + tid * 4];
    if (tid < 64) {
        *(float4*)&sxa[tid * 4] = *(const float4*)&g_xwagg[(size_t)n * 256 + tid * 4];
        semb[tid] = emb[(size_t)n * 64 + tid];
    }
    __syncthreads();

    #pragma unroll
    for (int q = 0; q < 4; q++) {
        int s = tid + 128 * q;
        int b = s >> 5, o = s & 31;
        float a = 0.0f;
        #pragma unroll
        for (int k = 0; k < 3; k++)
            #pragma unroll
            for (int i = 0; i < 32; i++)
                a = fmaf(sx[k][b * 32 + i], sW[k * 1024 + i * 32 + o], a);
        sg[s] = a;
        float w = 0.0f;
        #pragma unroll
        for (int i = 0; i < 16; i++)
            w = fmaf(sxa[b * 16 + i], sww[i * 32 + o], w);
        sw2[s] = w;
    }
    if (tid < 64) {
        float bsum = 0.0f;
        #pragma unroll
        for (int d = 0; d < 64; d++)
            bsum = fmaf(semb[d], __ldg(&bpool[d * 64 + tid]), bsum);
        sbias[tid] = bsum;
    }
    __syncthreads();

    if (tid < 16) {
        float s1 = 0, q1 = 0, s2 = 0, q2 = 0;
        #pragma unroll
        for (int o = 0; o < 32; o++) {
            float v = sg[tid * 32 + o];
            s1 += v; q1 = fmaf(v, v, q1);
            float u = sw2[tid * 32 + o];
            s2 += u; q2 = fmaf(u, u, q2);
        }
        float mu1 = s1 * (1.0f / 32.0f), mu2 = s2 * (1.0f / 32.0f);
        smu[tid] = mu1;
        srs[tid] = rsqrtf(fmaxf(q1 * (1.0f / 32.0f) - mu1 * mu1, 0.0f) + 1e-5f);
        smu2[tid] = mu2;
        srs2[tid] = rsqrtf(fmaxf(q2 * (1.0f / 32.0f) - mu2 * mu2, 0.0f) + 1e-5f);
    }
    __syncthreads();

    #pragma unroll
    for (int q = 0; q < 8; q++) {
        int s = tid + 128 * q;
        int b = s >> 6, h = s & 63;
        float v;
        if (h < 32)
            v = (sg[b * 32 + h] - smu[b]) * srs[b] * __ldg(&ln1w[h]) + __ldg(&ln1b[h]);
        else
            v = (sw2[b * 32 + h - 32] - smu2[b]) * srs2[b] * __ldg(&ln2w[h - 32]) + __ldg(&ln2b[h - 32]);
        out[((size_t)b * Nn + n) * 64 + h] = v + sbias[h];
    }
}

extern "C" void kernel_launch(void* const* d_in, const int* in_sizes, int n_in,
                              void* d_out, int out_size) {
    const float* x    = (const float*)d_in[0];
    const float* xw   = (const float*)d_in[1];
    const float* emb  = (const float*)d_in[2];
    const float* wp   = (const float*)d_in[3];
    const float* wwin = (const float*)d_in[4];
    const float* bp   = (const float*)d_in[5];
    const float* T    = (const float*)d_in[6];
    const float* l1w  = (const float*)d_in[7];
    const float* l1b  = (const float*)d_in[8];
    const float* l2w  = (const float*)d_in[9];
    const float* l2b  = (const float*)d_in[10];
    float* out = (float*)d_out;

    cudaFuncSetAttribute(pexp_tc, cudaFuncAttributeMaxDynamicSharedMemorySize, PE_SMEM);
    cudaFuncSetAttribute(tc_gemm, cudaFuncAttributeMaxDynamicSharedMemorySize, SMEM_BYTES);

    prep_kernel<<<652, 256>>>(x, emb);                       // 0
    rowmax_tc<<<dim3(2, 40), 256>>>();                       // 1
    pexp_tc<<<dim3(4, 40), 256, PE_SMEM>>>();                // 2
    tc_gemm<<<dim3(4, 32), 256, SMEM_BYTES>>>(0);            // 3  <- profiled slot
    tc_gemm<<<dim3(4, 32), 256, SMEM_BYTES>>>(1);            // 4
    xwagg_kernel<<<(Nn * Bb * 16 + 255) / 256, 256>>>(xw, T);// 5
    pool_gemm<<<dim3(24, 157), 128>>>(emb, wp, 3072, 0);     // 6
    pool_gemm<<<dim3(4, 157), 128>>>(emb, wwin, 512, 1);     // 7
    final_kernel<<<Nn, 128>>>(x, emb, bp, l1w, l1b, l2w, l2b, out); // 8
}

// round 12
// speedup vs baseline: 4.5757x; 1.3386x over previous
#include <cuda_runtime.h>
#include <cuda_fp16.h>
#include <cstdint>

#define Nn   5000
#define Bb   16
#define MP   5120          // padded node dim, 40*128 = 32*160
#define NK   80            // MP/64 k-chunks

// ---------------- scratch (device globals, zero-initialized at load) ----------------
__device__ __half g_Eh[(size_t)MP * 64];
__device__ __half g_El[(size_t)MP * 64];
__device__ float g_rowmax[MP];            // atomicMax (idempotent across replays)
__device__ float g_rsp[4][MP];            // rowsum partials per n-chunk
__device__ __half g_Ph[(size_t)MP * MP];  // P (single fp16 limb)
__device__ __half g_xT_h[(size_t)512 * MP];
__device__ __half g_y1T_h[(size_t)512 * MP];
__device__ float g_y1[(size_t)Nn * 512];
__device__ float g_y2[(size_t)Nn * 512];
__device__ __half g_WT[(size_t)3584 * 64];      // [wp|wwin]^T fp16, K-major
__device__ __half g_W16[(size_t)MP * 3584];     // per-node weights fp16
__device__ float g_xwagg[Nn * Bb * 16];

// ---------------- base-ISA tensor helpers ----------------
__device__ __forceinline__ void cpa16(uint32_t s, const void* g) {
    asm volatile("cp.async.cg.shared.global [%0], [%1], 16;" :: "r"(s), "l"(g) : "memory");
}
__device__ __forceinline__ void ldsm4(uint32_t* r, uint32_t a) {
    asm volatile("ldmatrix.sync.aligned.m8n8.x4.shared.b16 {%0,%1,%2,%3}, [%4];"
                 : "=r"(r[0]), "=r"(r[1]), "=r"(r[2]), "=r"(r[3]) : "r"(a));
}
__device__ __forceinline__ void ldsm2(uint32_t* r, uint32_t a) {
    asm volatile("ldmatrix.sync.aligned.m8n8.x2.shared.b16 {%0,%1}, [%2];"
                 : "=r"(r[0]), "=r"(r[1]) : "r"(a));
}
__device__ __forceinline__ void mma_h(float* d, const uint32_t* a, const uint32_t* b) {
    asm volatile("mma.sync.aligned.m16n8k16.row.col.f32.f16.f16.f32 "
                 "{%0,%1,%2,%3}, {%4,%5,%6,%7}, {%8,%9}, {%0,%1,%2,%3};"
                 : "+f"(d[0]), "+f"(d[1]), "+f"(d[2]), "+f"(d[3])
                 : "r"(a[0]), "r"(a[1]), "r"(a[2]), "r"(a[3]), "r"(b[0]), "r"(b[1]));
}
__device__ __forceinline__ uint32_t pack2h(float a, float b) {
    __half2 h = __halves2half2(__float2half_rn(a), __float2half_rn(b));
    return *(uint32_t*)&h;
}
__device__ __forceinline__ uint32_t smem_u32(const void* p) {
    uint32_t r;
    asm("{ .reg .u64 t; cvta.to.shared.u64 t, %1; cvt.u32.u64 %0, t; }" : "=r"(r) : "l"(p));
    return r;
}

// ---------------- prep: x transpose (fp16) + emb limbs + weight transpose ----------------
__global__ void prep_kernel(const float* __restrict__ x, const float* __restrict__ emb,
                            const float* __restrict__ wp, const float* __restrict__ wwin) {
    __shared__ float t[64][65];
    if (blockIdx.x < 632) {
        int mt = blockIdx.x % 79, jt = blockIdx.x / 79;
        int m0 = mt * 64, j0 = jt * 64;
        #pragma unroll
        for (int q = 0; q < 16; q++) {
            int f = threadIdx.x + 256 * q;
            int mr = f >> 6, jj = f & 63;
            int m = m0 + mr, j = j0 + jj;
            float v = (m < Nn) ? x[(((size_t)(j >> 5)) * Nn + m) * 32 + (j & 31)] : 0.0f;
            t[jj][mr] = v;
        }
        __syncthreads();
        #pragma unroll
        for (int q = 0; q < 16; q++) {
            int f = threadIdx.x + 256 * q;
            int jj = f >> 6, mr = f & 63;
            int m = m0 + mr;
            if (m < Nn)
                g_xT_h[(size_t)(j0 + jj) * MP + m] = __float2half_rn(t[jj][mr]);
        }
    } else if (blockIdx.x < 652) {
        int gid = (blockIdx.x - 632) * 256 + threadIdx.x;
        for (int i = gid; i < Nn * 64; i += 20 * 256) {
            float v = emb[i];
            __half h = __float2half_rn(v);
            g_Eh[i] = h;
            g_El[i] = __float2half_rn(v - __half2float(h));
        }
    } else {
        int j = (blockIdx.x - 652) * 256 + threadIdx.x;   // 0..3583
        #pragma unroll 8
        for (int d = 0; d < 64; d++) {
            float v = (j < 3072) ? wp[(size_t)d * 3072 + j]
                                 : wwin[(size_t)d * 512 + (j - 3072)];
            g_WT[(size_t)j * 64 + d] = __float2half_rn(v);
        }
    }
}

// ---------------- rowmax: 1-pass fp16 relu(E E^T) row max ----------------
__global__ void __launch_bounds__(256) rowmax_tc() {
    __shared__ __align__(16) char sm[33280];
    uint32_t raw = smem_u32(sm);
    uint32_t SAH = raw, SBH = raw + 16384;
    unsigned* smax = (unsigned*)(sm + 32768);
    int tid = threadIdx.x, lane = tid & 31, wid = tid >> 5;
    int wm = wid >> 2, wn = wid & 3;
    int m0 = blockIdx.y * 128, nb = blockIdx.x * 2560;

    #pragma unroll
    for (int q = 0; q < 4; q++) {
        int u = tid + 256 * q;
        int row = u >> 3, c16 = u & 7;
        uint4 v = *(const uint4*)(g_Eh + (size_t)(m0 + row) * 64 + c16 * 8);
        *(uint4*)(sm + (row * 128 + ((c16 ^ (row & 7)) * 16))) = v;
    }
    if (tid < 128) smax[tid] = 0u;
    __syncthreads();

    int hb = lane >> 4, bbit = (lane >> 3) & 1;
    uint32_t a_off[4], a7[4], b_off[4], b7[4];
    #pragma unroll
    for (int mf = 0; mf < 4; mf++) {
        int ar = wm * 64 + mf * 16 + (lane & 15);
        a_off[mf] = (uint32_t)(ar * 128); a7[mf] = (uint32_t)(ar & 7);
    }
    #pragma unroll
    for (int nf = 0; nf < 4; nf++) {
        int br = wn * 32 + nf * 8 + (lane & 7);
        b_off[nf] = (uint32_t)(br * 128); b7[nf] = (uint32_t)(br & 7);
    }

    float rmx[4][2];
    #pragma unroll
    for (int mf = 0; mf < 4; mf++) { rmx[mf][0] = 0.0f; rmx[mf][1] = 0.0f; }

    for (int sub = 0; sub < 20; sub++) {
        int n0 = nb + sub * 128;
        #pragma unroll
        for (int q = 0; q < 4; q++) {
            int u = tid + 256 * q;
            int row = u >> 3, c16 = u & 7;
            uint4 v = *(const uint4*)(g_Eh + (size_t)(n0 + row) * 64 + c16 * 8);
            *(uint4*)(sm + 16384 + (row * 128 + ((c16 ^ (row & 7)) * 16))) = v;
        }
        __syncthreads();
        float acc[4][4][4];
        #pragma unroll
        for (int mf = 0; mf < 4; mf++)
            #pragma unroll
            for (int nf = 0; nf < 4; nf++)
                #pragma unroll
                for (int e = 0; e < 4; e++) acc[mf][nf][e] = 0.0f;
        #pragma unroll
        for (int ks = 0; ks < 4; ks++) {
            uint32_t af[4][4], bfx[4][2];
            uint32_t ca = (uint32_t)(ks * 2 + hb), cb = (uint32_t)(ks * 2 + bbit);
            #pragma unroll
            for (int mf = 0; mf < 4; mf++) ldsm4(af[mf], SAH + a_off[mf] + ((ca ^ a7[mf]) << 4));
            #pragma unroll
            for (int nf = 0; nf < 4; nf++) ldsm2(bfx[nf], SBH + b_off[nf] + ((cb ^ b7[nf]) << 4));
            #pragma unroll
            for (int mf = 0; mf < 4; mf++)
                #pragma unroll
                for (int nf = 0; nf < 4; nf++) mma_h(acc[mf][nf], af[mf], bfx[nf]);
        }
        #pragma unroll
        for (int mf = 0; mf < 4; mf++)
            #pragma unroll
            for (int nf = 0; nf < 4; nf++) {
                rmx[mf][0] = fmaxf(rmx[mf][0], fmaxf(acc[mf][nf][0], acc[mf][nf][1]));
                rmx[mf][1] = fmaxf(rmx[mf][1], fmaxf(acc[mf][nf][2], acc[mf][nf][3]));
            }
        __syncthreads();
    }
    int g = lane >> 2;
    #pragma unroll
    for (int mf = 0; mf < 4; mf++) {
        int r1 = wm * 64 + mf * 16 + g;
        atomicMax(&smax[r1], __float_as_uint(rmx[mf][0]));
        atomicMax(&smax[r1 + 8], __float_as_uint(rmx[mf][1]));
    }
    __syncthreads();
    if (tid < 128) atomicMax((unsigned*)&g_rowmax[m0 + tid], smax[tid]);
}

// ---------------- pexp: 3-pass fp16 logits + relu + exp + P fp16 + rowsum ----------------
#define PE_SMEM 101376
__global__ void __launch_bounds__(256) pexp_tc() {
    extern __shared__ char sm[];
    uint32_t raw = smem_u32(sm);
    uint32_t SAH = raw, SAL = raw + 16384, SBH = raw + 32768, SBL = raw + 49152;
    float* stg   = (float*)(sm + 32768);     // overlaps B tiles (phased)
    float* rsum  = (float*)(sm + 100352);
    float* rmaxS = (float*)(sm + 100864);

    int tid = threadIdx.x, lane = tid & 31, wid = tid >> 5;
    int wm = wid >> 2, wn = wid & 3;
    int m0 = blockIdx.y * 128, nc0 = blockIdx.x * 1280;

    #pragma unroll
    for (int q = 0; q < 8; q++) {
        int id = tid + 256 * q;
        int hf = id >> 10, u = id & 1023;
        int row = u >> 3, c16 = u & 7;
        const __half* src = hf ? g_El : g_Eh;
        uint4 v = *(const uint4*)(src + (size_t)(m0 + row) * 64 + c16 * 8);
        *(uint4*)(sm + (hf ? 16384 : 0) + row * 128 + ((c16 ^ (row & 7)) * 16)) = v;
    }
    if (tid < 128) { rsum[tid] = 0.0f; rmaxS[tid] = g_rowmax[m0 + tid]; }
    __syncthreads();

    int hb = lane >> 4, bbit = (lane >> 3) & 1;
    uint32_t a_off[4], a7[4], b_off[4], b7[4];
    #pragma unroll
    for (int mf = 0; mf < 4; mf++) {
        int ar = wm * 64 + mf * 16 + (lane & 15);
        a_off[mf] = (uint32_t)(ar * 128); a7[mf] = (uint32_t)(ar & 7);
    }
    #pragma unroll
    for (int nf = 0; nf < 4; nf++) {
        int br = wn * 32 + nf * 8 + (lane & 7);
        b_off[nf] = (uint32_t)(br * 128); b7[nf] = (uint32_t)(br & 7);
    }

    for (int sub = 0; sub < 10; sub++) {
        int n0 = nc0 + sub * 128;
        #pragma unroll
        for (int q = 0; q < 8; q++) {
            int id = tid + 256 * q;
            int hf = id >> 10, u = id & 1023;
            int row = u >> 3, c16 = u & 7;
            const __half* src = hf ? g_El : g_Eh;
            uint4 v = *(const uint4*)(src + (size_t)(n0 + row) * 64 + c16 * 8);
            *(uint4*)(sm + (hf ? 49152 : 32768) + row * 128 + ((c16 ^ (row & 7)) * 16)) = v;
        }
        __syncthreads();

        float acc[4][4][4];
        #pragma unroll
        for (int mf = 0; mf < 4; mf++)
            #pragma unroll
            for (int nf = 0; nf < 4; nf++)
                #pragma unroll
                for (int e = 0; e < 4; e++) acc[mf][nf][e] = 0.0f;
        #pragma unroll
        for (int ks = 0; ks < 4; ks++) {
            uint32_t ah[4][4], al[4][4], bh[4][2], bl[4][2];
            uint32_t ca = (uint32_t)(ks * 2 + hb), cb = (uint32_t)(ks * 2 + bbit);
            #pragma unroll
            for (int mf = 0; mf < 4; mf++) {
                uint32_t xo = a_off[mf] + ((ca ^ a7[mf]) << 4);
                ldsm4(ah[mf], SAH + xo);
                ldsm4(al[mf], SAL + xo);
            }
            #pragma unroll
            for (int nf = 0; nf < 4; nf++) {
                uint32_t xo = b_off[nf] + ((cb ^ b7[nf]) << 4);
                ldsm2(bh[nf], SBH + xo);
                ldsm2(bl[nf], SBL + xo);
            }
            #pragma unroll
            for (int mf = 0; mf < 4; mf++)
                #pragma unroll
                for (int nf = 0; nf < 4; nf++) {
                    mma_h(acc[mf][nf], ah[mf], bh[nf]);
                    mma_h(acc[mf][nf], ah[mf], bl[nf]);
                    mma_h(acc[mf][nf], al[mf], bh[nf]);
                }
        }
        __syncthreads();   // mma done before staging overwrites B region

        int g = lane >> 2, t4 = lane & 3;
        #pragma unroll
        for (int mf = 0; mf < 4; mf++) {
            int r1 = wm * 64 + mf * 16 + g, r2 = r1 + 8;
            float mx1 = rmaxS[r1], mx2 = rmaxS[r2];
            #pragma unroll
            for (int nf = 0; nf < 4; nf++) {
                int c = wn * 32 + nf * 8 + t4 * 2;
                stg[r1 * 132 + c]     = __expf(fmaxf(acc[mf][nf][0], 0.0f) - mx1);
                stg[r1 * 132 + c + 1] = __expf(fmaxf(acc[mf][nf][1], 0.0f) - mx1);
                stg[r2 * 132 + c]     = __expf(fmaxf(acc[mf][nf][2], 0.0f) - mx2);
                stg[r2 * 132 + c + 1] = __expf(fmaxf(acc[mf][nf][3], 0.0f) - mx2);
            }
        }
        __syncthreads();

        if (tid < 128) {
            float s = 0.0f;
            #pragma unroll 8
            for (int c = 0; c < 128; c++) s += stg[tid * 132 + c];
            rsum[tid] += s;
        }
        // FULL tile store: 2048 uint4 units = 128 rows x 16 units x 8 halves = 128x128
        #pragma unroll
        for (int q = 0; q < 8; q++) {
            int id = tid + 256 * q;
            int row = id >> 4, cu = id & 15;
            uint32_t wh[4];
            #pragma unroll
            for (int p = 0; p < 4; p++)
                wh[p] = pack2h(stg[row * 132 + cu * 8 + 2 * p],
                               stg[row * 132 + cu * 8 + 2 * p + 1]);
            *(uint4*)(g_Ph + (size_t)(m0 + row) * MP + n0 + cu * 8) =
                make_uint4(wh[0], wh[1], wh[2], wh[3]);
        }
        __syncthreads();   // staging consumed before next B load
    }
    if (tid < 128) g_rsp[blockIdx.x][m0 + tid] = rsum[tid];
}

// ---------------- HMMA GEMM: C = diag(1/rowsum)*(P @ Bt^T), fp16 1-pass, 4-stage ----------------
#define MT 160
#define JT 128
#define ABYTES 20480
#define BBYTES 16384
#define STG    (ABYTES + BBYTES)          // 36864
#define SMEM_BYTES (1024 + 4 * STG)       // 148480
#define SST 132

__global__ void __launch_bounds__(256) tc_gemm(int which) {
    extern __shared__ char dsm[];
    uint32_t raw = smem_u32(dsm);
    uint32_t sb = (raw + 1023u) & ~1023u;

    int tid = threadIdx.x, lane = tid & 31, wid = tid >> 5;
    int wm = wid >> 2, wn = wid & 3;
    int m0 = blockIdx.y * MT, j0 = blockIdx.x * JT;

    const __half* __restrict__ BT = which ? g_y1T_h : g_xT_h;

    uint32_t sA[5], sB[4];
    size_t gA[5], gB[4];
    #pragma unroll
    for (int q = 0; q < 5; q++) {
        int u = tid + 256 * q;
        int row = u >> 3, c16 = u & 7;
        sA[q] = (uint32_t)(row * 128 + ((c16 ^ (row & 7)) * 16));
        gA[q] = (size_t)(m0 + row) * MP + c16 * 8;
    }
    #pragma unroll
    for (int q = 0; q < 4; q++) {
        int u = tid + 256 * q;
        int row = u >> 3, c16 = u & 7;
        sB[q] = (uint32_t)(row * 128 + ((c16 ^ (row & 7)) * 16));
        gB[q] = (size_t)(j0 + row) * MP + c16 * 8;
    }

    auto issue = [&](int t) {
        uint32_t base = sb + (uint32_t)(t & 3) * STG;
        size_t ko = (size_t)t * 64;
        #pragma unroll
        for (int q = 0; q < 5; q++) cpa16(base + sA[q], g_Ph + gA[q] + ko);
        #pragma unroll
        for (int q = 0; q < 4; q++) cpa16(base + ABYTES + sB[q], BT + gB[q] + ko);
        asm volatile("cp.async.commit_group;" ::: "memory");
    };

    uint32_t a_off[5], a7[5], b_off[4], b7[4];
    int hb = lane >> 4, bbit = (lane >> 3) & 1;
    #pragma unroll
    for (int mf = 0; mf < 5; mf++) {
        int ar = wm * 80 + mf * 16 + (lane & 15);
        a_off[mf] = (uint32_t)(ar * 128); a7[mf] = (uint32_t)(ar & 7);
    }
    #pragma unroll
    for (int nf = 0; nf < 4; nf++) {
        int br = wn * 32 + nf * 8 + (lane & 7);
        b_off[nf] = (uint32_t)(br * 128); b7[nf] = (uint32_t)(br & 7);
    }

    float acc[5][4][4];
    #pragma unroll
    for (int mf = 0; mf < 5; mf++)
        #pragma unroll
        for (int nf = 0; nf < 4; nf++)
            #pragma unroll
            for (int e = 0; e < 4; e++) acc[mf][nf][e] = 0.0f;

    issue(0); issue(1); issue(2);

    uint32_t af[2][5][4], bfr[2][4][2];
    for (int t = 0; t < NK; t++) {
        asm volatile("cp.async.wait_group 2;" ::: "memory");
        __syncthreads();
        if (t + 3 < NK) issue(t + 3);

        uint32_t Abuf = sb + (uint32_t)(t & 3) * STG;
        uint32_t Bbuf = Abuf + ABYTES;

        // prime ks=0 fragments
        {
            uint32_t ca = (uint32_t)hb, cb = (uint32_t)bbit;
            #pragma unroll
            for (int mf = 0; mf < 5; mf++) ldsm4(af[0][mf], Abuf + a_off[mf] + ((ca ^ a7[mf]) << 4));
            #pragma unroll
            for (int nf = 0; nf < 4; nf++) ldsm2(bfr[0][nf], Bbuf + b_off[nf] + ((cb ^ b7[nf]) << 4));
        }
        #pragma unroll
        for (int ks = 0; ks < 4; ks++) {
            int cur = ks & 1, nxt = cur ^ 1;
            if (ks < 3) {
                uint32_t ca = (uint32_t)((ks + 1) * 2 + hb), cb = (uint32_t)((ks + 1) * 2 + bbit);
                #pragma unroll
                for (int mf = 0; mf < 5; mf++) ldsm4(af[nxt][mf], Abuf + a_off[mf] + ((ca ^ a7[mf]) << 4));
                #pragma unroll
                for (int nf = 0; nf < 4; nf++) ldsm2(bfr[nxt][nf], Bbuf + b_off[nf] + ((cb ^ b7[nf]) << 4));
            }
            #pragma unroll
            for (int mf = 0; mf < 5; mf++)
                #pragma unroll
                for (int nf = 0; nf < 4; nf++)
                    mma_h(acc[mf][nf], af[cur][mf], bfr[cur][nf]);
        }
    }
    // DRAIN: in-flight cp.async groups target buffers overlapping the staging area.
    asm volatile("cp.async.wait_group 0;" ::: "memory");
    __syncthreads();

    // epilogue: alpha = 1/rowsum (4 partials, fixed order), stage, write
    float* st = (float*)(dsm + (sb - raw));
    int g = lane >> 2, t4 = lane & 3;
    #pragma unroll
    for (int mf = 0; mf < 5; mf++) {
        int r0 = wm * 80 + mf * 16 + g;
        int ma = m0 + r0, mb = ma + 8;
        float al0 = 0.0f, al1 = 0.0f;
        if (ma < Nn) al0 = 1.0f / (g_rsp[0][ma] + g_rsp[1][ma] + g_rsp[2][ma] + g_rsp[3][ma]);
        if (mb < Nn) al1 = 1.0f / (g_rsp[0][mb] + g_rsp[1][mb] + g_rsp[2][mb] + g_rsp[3][mb]);
        #pragma unroll
        for (int nf = 0; nf < 4; nf++) {
            int c0 = wn * 32 + nf * 8 + t4 * 2;
            st[r0 * SST + c0]           = acc[mf][nf][0] * al0;
            st[r0 * SST + c0 + 1]       = acc[mf][nf][1] * al0;
            st[(r0 + 8) * SST + c0]     = acc[mf][nf][2] * al1;
            st[(r0 + 8) * SST + c0 + 1] = acc[mf][nf][3] * al1;
        }
    }
    __syncthreads();

    float* __restrict__ Y = which ? g_y2 : g_y1;
    for (int u = tid; u < MT * 32; u += 256) {
        int r = u >> 5, ch = u & 31;
        int m = m0 + r;
        if (m < Nn) {
            float4 v = {st[r * SST + ch * 4],     st[r * SST + ch * 4 + 1],
                        st[r * SST + ch * 4 + 2], st[r * SST + ch * 4 + 3]};
            *(float4*)&Y[(size_t)m * 512 + j0 + ch * 4] = v;
        }
    }
    if (which == 0) {
        for (int u = tid; u < JT * 20; u += 256) {
            int j = u / 20, mm = u % 20;
            uint32_t w[4];
            #pragma unroll
            for (int p = 0; p < 4; p++)
                w[p] = pack2h(st[(mm * 8 + 2 * p) * SST + j],
                              st[(mm * 8 + 2 * p + 1) * SST + j]);
            *(uint4*)&g_y1T_h[(size_t)(j0 + j) * MP + m0 + mm * 8] =
                make_uint4(w[0], w[1], w[2], w[3]);
        }
    }
}

// ---------------- pool_tc: W16[n][j] = sum_d emb2limb[n,d] * WT[j,d], fp16 out ----------------
__global__ void __launch_bounds__(256) pool_tc() {
    __shared__ __align__(16) char sm[49152];
    uint32_t raw = smem_u32(sm);
    uint32_t SAH = raw, SAL = raw + 16384, SBH = raw + 32768;
    int tid = threadIdx.x, lane = tid & 31, wid = tid >> 5;
    int wm = wid >> 2, wn = wid & 3;
    int m0 = blockIdx.y * 128, j0 = blockIdx.x * 128;

    #pragma unroll
    for (int q = 0; q < 4; q++) {
        int u = tid + 256 * q;
        int row = u >> 3, c16 = u & 7;
        uint32_t so = (uint32_t)(row * 128 + ((c16 ^ (row & 7)) * 16));
        *(uint4*)(sm + so)          = *(const uint4*)(g_Eh + (size_t)(m0 + row) * 64 + c16 * 8);
        *(uint4*)(sm + 16384 + so)  = *(const uint4*)(g_El + (size_t)(m0 + row) * 64 + c16 * 8);
        *(uint4*)(sm + 32768 + so)  = *(const uint4*)(g_WT + (size_t)(j0 + row) * 64 + c16 * 8);
    }
    __syncthreads();

    int hb = lane >> 4, bbit = (lane >> 3) & 1;
    uint32_t a_off[4], a7[4], b_off[4], b7[4];
    #pragma unroll
    for (int mf = 0; mf < 4; mf++) {
        int ar = wm * 64 + mf * 16 + (lane & 15);
        a_off[mf] = (uint32_t)(ar * 128); a7[mf] = (uint32_t)(ar & 7);
    }
    #pragma unroll
    for (int nf = 0; nf < 4; nf++) {
        int br = wn * 32 + nf * 8 + (lane & 7);
        b_off[nf] = (uint32_t)(br * 128); b7[nf] = (uint32_t)(br & 7);
    }

    float acc[4][4][4];
    #pragma unroll
    for (int mf = 0; mf < 4; mf++)
        #pragma unroll
        for (int nf = 0; nf < 4; nf++)
            #pragma unroll
            for (int e = 0; e < 4; e++) acc[mf][nf][e] = 0.0f;

    #pragma unroll
    for (int ks = 0; ks < 4; ks++) {
        uint32_t ah[4][4], al[4][4], bh[4][2];
        uint32_t ca = (uint32_t)(ks * 2 + hb), cb = (uint32_t)(ks * 2 + bbit);
        #pragma unroll
        for (int mf = 0; mf < 4; mf++) {
            uint32_t xo = a_off[mf] + ((ca ^ a7[mf]) << 4);
            ldsm4(ah[mf], SAH + xo);
            ldsm4(al[mf], SAL + xo);
        }
        #pragma unroll
        for (int nf = 0; nf < 4; nf++) ldsm2(bh[nf], SBH + b_off[nf] + ((cb ^ b7[nf]) << 4));
        #pragma unroll
        for (int mf = 0; mf < 4; mf++)
            #pragma unroll
            for (int nf = 0; nf < 4; nf++) {
                mma_h(acc[mf][nf], ah[mf], bh[nf]);
                mma_h(acc[mf][nf], al[mf], bh[nf]);
            }
    }

    int g = lane >> 2, t4 = lane & 3;
    #pragma unroll
    for (int mf = 0; mf < 4; mf++) {
        int r1 = m0 + wm * 64 + mf * 16 + g;
        #pragma unroll
        for (int nf = 0; nf < 4; nf++) {
            int c = j0 + wn * 32 + nf * 8 + t4 * 2;
            *(uint32_t*)&g_W16[(size_t)r1 * 3584 + c] = pack2h(acc[mf][nf][0], acc[mf][nf][1]);
            *(uint32_t*)&g_W16[(size_t)(r1 + 8) * 3584 + c] = pack2h(acc[mf][nf][2], acc[mf][nf][3]);
        }
    }
}

// ---------------- xwagg ----------------
__global__ void xwagg_kernel(const float* __restrict__ xw, const float* __restrict__ T) {
    int idx = blockIdx.x * 256 + threadIdx.x;
    if (idx >= Nn * Bb * 16) return;
    int n = idx >> 8, r = idx & 255, b = r >> 4, i = r & 15;
    float s = 0.0f;
    #pragma unroll
    for (int t = 0; t < 12; t++)
        s = fmaf(__ldg(&T[t]), xw[(((size_t)b * 12 + t) * Nn + n) * 16 + i], s);
    g_xwagg[idx] = s;
}

// ---------------- fused epilogue ----------------
__global__ void __launch_bounds__(128) final_kernel(const float* __restrict__ x,
                                                    const float* __restrict__ emb,
                                                    const float* __restrict__ bpool,
                                                    const float* __restrict__ ln1w,
                                                    const float* __restrict__ ln1b,
                                                    const float* __restrict__ ln2w,
                                                    const float* __restrict__ ln2b,
                                                    float* __restrict__ out) {
    int n = blockIdx.x;
    int tid = threadIdx.x;
    __shared__ float sW[3072];
    __shared__ float sww[512];
    __shared__ float sx[3][512];
    __shared__ float sxa[256];
    __shared__ float sg[512];
    __shared__ float sw2[512];
    __shared__ float semb[64];
    __shared__ float sbias[64];
    __shared__ float smu[16], srs[16], smu2[16], srs2[16];

    for (int u = tid; u < 448; u += 128) {
        uint4 v = *(const uint4*)&g_W16[(size_t)n * 3584 + u * 8];
        const __half* h = (const __half*)&v;
        int base = u * 8;
        if (base < 3072) {
            #pragma unroll
            for (int p = 0; p < 8; p++) sW[base + p] = __half2float(h[p]);
        } else {
            #pragma unroll
            for (int p = 0; p < 8; p++) sww[base - 3072 + p] = __half2float(h[p]);
        }
    }
    {
        int b = tid >> 3, i4 = (tid & 7) * 4;
        *(float4*)&sx[0][tid * 4] = *(const float4*)&x[((size_t)b * Nn + n) * 32 + i4];
    }
    *(float4*)&sx[1][tid * 4] = *(const float4*)&g_y1[(size_t)n * 512 + tid * 4];
    *(float4*)&sx[2][tid * 4] = *(const float4*)&g_y2[(size_t)n * 512 + tid * 4];
    if (tid < 64) {
        *(float4*)&sxa[tid * 4] = *(const float4*)&g_xwagg[(size_t)n * 256 + tid * 4];
        semb[tid] = emb[(size_t)n * 64 + tid];
    }
    __syncthreads();

    #pragma unroll
    for (int q = 0; q < 4; q++) {
        int s = tid + 128 * q;
        int b = s >> 5, o = s & 31;
        float a = 0.0f;
        #pragma unroll
        for (int k = 0; k < 3; k++)
            #pragma unroll
            for (int i = 0; i < 32; i++)
                a = fmaf(sx[k][b * 32 + i], sW[k * 1024 + i * 32 + o], a);
        sg[s] = a;
        float w = 0.0f;
        #pragma unroll
        for (int i = 0; i < 16; i++)
            w = fmaf(sxa[b * 16 + i], sww[i * 32 + o], w);
        sw2[s] = w;
    }
    if (tid < 64) {
        float bsum = 0.0f;
        #pragma unroll
        for (int d = 0; d < 64; d++)
            bsum = fmaf(semb[d], __ldg(&bpool[d * 64 + tid]), bsum);
        sbias[tid] = bsum;
    }
    __syncthreads();

    if (tid < 16) {
        float s1 = 0, q1 = 0, s2 = 0, q2 = 0;
        #pragma unroll
        for (int o = 0; o < 32; o++) {
            float v = sg[tid * 32 + o];
            s1 += v; q1 = fmaf(v, v, q1);
            float u = sw2[tid * 32 + o];
            s2 += u; q2 = fmaf(u, u, q2);
        }
        float mu1 = s1 * (1.0f / 32.0f), mu2 = s2 * (1.0f / 32.0f);
        smu[tid] = mu1;
        srs[tid] = rsqrtf(fmaxf(q1 * (1.0f / 32.0f) - mu1 * mu1, 0.0f) + 1e-5f);
        smu2[tid] = mu2;
        srs2[tid] = rsqrtf(fmaxf(q2 * (1.0f / 32.0f) - mu2 * mu2, 0.0f) + 1e-5f);
    }
    __syncthreads();

    #pragma unroll
    for (int q = 0; q < 8; q++) {
        int s = tid + 128 * q;
        int b = s >> 6, h = s & 63;
        float v;
        if (h < 32)
            v = (sg[b * 32 + h] - smu[b]) * srs[b] * __ldg(&ln1w[h]) + __ldg(&ln1b[h]);
        else
            v = (sw2[b * 32 + h - 32] - smu2[b]) * srs2[b] * __ldg(&ln2w[h - 32]) + __ldg(&ln2b[h - 32]);
        out[((size_t)b * Nn + n) * 64 + h] = v + sbias[h];
    }
}

extern "C" void kernel_launch(void* const* d_in, const int* in_sizes, int n_in,
                              void* d_out, int out_size) {
    const float* x    = (const float*)d_in[0];
    const float* xw   = (const float*)d_in[1];
    const float* emb  = (const float*)d_in[2];
    const float* wp   = (const float*)d_in[3];
    const float* wwin = (const float*)d_in[4];
    const float* bp   = (const float*)d_in[5];
    const float* T    = (const float*)d_in[6];
    const float* l1w  = (const float*)d_in[7];
    const float* l1b  = (const float*)d_in[8];
    const float* l2w  = (const float*)d_in[9];
    const float* l2b  = (const float*)d_in[10];
    float* out = (float*)d_out;

    cudaFuncSetAttribute(pexp_tc, cudaFuncAttributeMaxDynamicSharedMemorySize, PE_SMEM);
    cudaFuncSetAttribute(tc_gemm, cudaFuncAttributeMaxDynamicSharedMemorySize, SMEM_BYTES);

    prep_kernel<<<666, 256>>>(x, emb, wp, wwin);             // 0
    rowmax_tc<<<dim3(2, 40), 256>>>();                       // 1
    pexp_tc<<<dim3(4, 40), 256, PE_SMEM>>>();                // 2
    tc_gemm<<<dim3(4, 32), 256, SMEM_BYTES>>>(0);            // 3  <- profiled slot
    tc_gemm<<<dim3(4, 32), 256, SMEM_BYTES>>>(1);            // 4
    pool_tc<<<dim3(28, 40), 256>>>();                        // 5
    xwagg_kernel<<<(Nn * Bb * 16 + 255) / 256, 256>>>(xw, T);// 6
    final_kernel<<<Nn, 128>>>(x, emb, bp, l1w, l1b, l2w, l2b, out); // 7
}

// round 13
// speedup vs baseline: 4.6597x; 1.0184x over previous
#include <cuda_runtime.h>
#include <cuda_fp16.h>
#include <cstdint>

#define Nn   5000
#define Bb   16
#define MP   5120          // padded node dim, 40*128 = 32*160
#define NK   80            // MP/64 k-chunks

// ---------------- scratch (device globals, zero-initialized at load) ----------------
__device__ __half g_Eh[(size_t)MP * 64];
__device__ __half g_El[(size_t)MP * 64];
__device__ float g_rowmax[MP];
__device__ float g_rsp[4][MP];
__device__ __half g_Ph[(size_t)MP * MP];
__device__ __half g_xT_h[(size_t)512 * MP];
__device__ __half g_y1T_h[(size_t)512 * MP];
__device__ float g_y1[(size_t)Nn * 512];
__device__ float g_y2[(size_t)Nn * 512];
__device__ __half g_WT[(size_t)3584 * 64];
__device__ __half g_W16[(size_t)MP * 3584];
__device__ float g_xwagg[Nn * Bb * 16];

// ---------------- base-ISA tensor helpers ----------------
__device__ __forceinline__ void cpa16(uint32_t s, const void* g) {
    asm volatile("cp.async.cg.shared.global [%0], [%1], 16;" :: "r"(s), "l"(g) : "memory");
}
__device__ __forceinline__ void ldsm4(uint32_t* r, uint32_t a) {
    asm volatile("ldmatrix.sync.aligned.m8n8.x4.shared.b16 {%0,%1,%2,%3}, [%4];"
                 : "=r"(r[0]), "=r"(r[1]), "=r"(r[2]), "=r"(r[3]) : "r"(a));
}
__device__ __forceinline__ void ldsm2(uint32_t* r, uint32_t a) {
    asm volatile("ldmatrix.sync.aligned.m8n8.x2.shared.b16 {%0,%1}, [%2];"
                 : "=r"(r[0]), "=r"(r[1]) : "r"(a));
}
__device__ __forceinline__ void mma_h(float* d, const uint32_t* a, const uint32_t* b) {
    asm volatile("mma.sync.aligned.m16n8k16.row.col.f32.f16.f16.f32 "
                 "{%0,%1,%2,%3}, {%4,%5,%6,%7}, {%8,%9}, {%0,%1,%2,%3};"
                 : "+f"(d[0]), "+f"(d[1]), "+f"(d[2]), "+f"(d[3])
                 : "r"(a[0]), "r"(a[1]), "r"(a[2]), "r"(a[3]), "r"(b[0]), "r"(b[1]));
}
__device__ __forceinline__ uint32_t pack2h(float a, float b) {
    __half2 h = __halves2half2(__float2half_rn(a), __float2half_rn(b));
    return *(uint32_t*)&h;
}
__device__ __forceinline__ uint32_t smem_u32(const void* p) {
    uint32_t r;
    asm("{ .reg .u64 t; cvta.to.shared.u64 t, %1; cvt.u32.u64 %0, t; }" : "=r"(r) : "l"(p));
    return r;
}

// ---------------- prep ----------------
__global__ void prep_kernel(const float* __restrict__ x, const float* __restrict__ emb,
                            const float* __restrict__ wp, const float* __restrict__ wwin) {
    __shared__ float t[64][65];
    if (blockIdx.x < 632) {
        int mt = blockIdx.x % 79, jt = blockIdx.x / 79;
        int m0 = mt * 64, j0 = jt * 64;
        #pragma unroll
        for (int q = 0; q < 16; q++) {
            int f = threadIdx.x + 256 * q;
            int mr = f >> 6, jj = f & 63;
            int m = m0 + mr, j = j0 + jj;
            float v = (m < Nn) ? x[(((size_t)(j >> 5)) * Nn + m) * 32 + (j & 31)] : 0.0f;
            t[jj][mr] = v;
        }
        __syncthreads();
        #pragma unroll
        for (int q = 0; q < 16; q++) {
            int f = threadIdx.x + 256 * q;
            int jj = f >> 6, mr = f & 63;
            int m = m0 + mr;
            if (m < Nn)
                g_xT_h[(size_t)(j0 + jj) * MP + m] = __float2half_rn(t[jj][mr]);
        }
    } else if (blockIdx.x < 652) {
        int gid = (blockIdx.x - 632) * 256 + threadIdx.x;
        for (int i = gid; i < Nn * 64; i += 20 * 256) {
            float v = emb[i];
            __half h = __float2half_rn(v);
            g_Eh[i] = h;
            g_El[i] = __float2half_rn(v - __half2float(h));
        }
    } else {
        int j = (blockIdx.x - 652) * 256 + threadIdx.x;
        #pragma unroll 8
        for (int d = 0; d < 64; d++) {
            float v = (j < 3072) ? wp[(size_t)d * 3072 + j]
                                 : wwin[(size_t)d * 512 + (j - 3072)];
            g_WT[(size_t)j * 64 + d] = __float2half_rn(v);
        }
    }
}

// ---------------- rowmax ----------------
__global__ void __launch_bounds__(256) rowmax_tc() {
    __shared__ __align__(16) char sm[33280];
    uint32_t raw = smem_u32(sm);
    uint32_t SAH = raw, SBH = raw + 16384;
    unsigned* smax = (unsigned*)(sm + 32768);
    int tid = threadIdx.x, lane = tid & 31, wid = tid >> 5;
    int wm = wid >> 2, wn = wid & 3;
    int m0 = blockIdx.y * 128, nb = blockIdx.x * 2560;

    #pragma unroll
    for (int q = 0; q < 4; q++) {
        int u = tid + 256 * q;
        int row = u >> 3, c16 = u & 7;
        uint4 v = *(const uint4*)(g_Eh + (size_t)(m0 + row) * 64 + c16 * 8);
        *(uint4*)(sm + (row * 128 + ((c16 ^ (row & 7)) * 16))) = v;
    }
    if (tid < 128) smax[tid] = 0u;
    __syncthreads();

    int hb = lane >> 4, bbit = (lane >> 3) & 1;
    uint32_t a_off[4], a7[4], b_off[4], b7[4];
    #pragma unroll
    for (int mf = 0; mf < 4; mf++) {
        int ar = wm * 64 + mf * 16 + (lane & 15);
        a_off[mf] = (uint32_t)(ar * 128); a7[mf] = (uint32_t)(ar & 7);
    }
    #pragma unroll
    for (int nf = 0; nf < 4; nf++) {
        int br = wn * 32 + nf * 8 + (lane & 7);
        b_off[nf] = (uint32_t)(br * 128); b7[nf] = (uint32_t)(br & 7);
    }

    float rmx[4][2];
    #pragma unroll
    for (int mf = 0; mf < 4; mf++) { rmx[mf][0] = 0.0f; rmx[mf][1] = 0.0f; }

    for (int sub = 0; sub < 20; sub++) {
        int n0 = nb + sub * 128;
        #pragma unroll
        for (int q = 0; q < 4; q++) {
            int u = tid + 256 * q;
            int row = u >> 3, c16 = u & 7;
            uint4 v = *(const uint4*)(g_Eh + (size_t)(n0 + row) * 64 + c16 * 8);
            *(uint4*)(sm + 16384 + (row * 128 + ((c16 ^ (row & 7)) * 16))) = v;
        }
        __syncthreads();
        float acc[4][4][4];
        #pragma unroll
        for (int mf = 0; mf < 4; mf++)
            #pragma unroll
            for (int nf = 0; nf < 4; nf++)
                #pragma unroll
                for (int e = 0; e < 4; e++) acc[mf][nf][e] = 0.0f;
        #pragma unroll
        for (int ks = 0; ks < 4; ks++) {
            uint32_t af[4][4], bfx[4][2];
            uint32_t ca = (uint32_t)(ks * 2 + hb), cb = (uint32_t)(ks * 2 + bbit);
            #pragma unroll
            for (int mf = 0; mf < 4; mf++) ldsm4(af[mf], SAH + a_off[mf] + ((ca ^ a7[mf]) << 4));
            #pragma unroll
            for (int nf = 0; nf < 4; nf++) ldsm2(bfx[nf], SBH + b_off[nf] + ((cb ^ b7[nf]) << 4));
            #pragma unroll
            for (int mf = 0; mf < 4; mf++)
                #pragma unroll
                for (int nf = 0; nf < 4; nf++) mma_h(acc[mf][nf], af[mf], bfx[nf]);
        }
        #pragma unroll
        for (int mf = 0; mf < 4; mf++)
            #pragma unroll
            for (int nf = 0; nf < 4; nf++) {
                rmx[mf][0] = fmaxf(rmx[mf][0], fmaxf(acc[mf][nf][0], acc[mf][nf][1]));
                rmx[mf][1] = fmaxf(rmx[mf][1], fmaxf(acc[mf][nf][2], acc[mf][nf][3]));
            }
        __syncthreads();
    }
    int g = lane >> 2;
    #pragma unroll
    for (int mf = 0; mf < 4; mf++) {
        int r1 = wm * 64 + mf * 16 + g;
        atomicMax(&smax[r1], __float_as_uint(rmx[mf][0]));
        atomicMax(&smax[r1 + 8], __float_as_uint(rmx[mf][1]));
    }
    __syncthreads();
    if (tid < 128) atomicMax((unsigned*)&g_rowmax[m0 + tid], smax[tid]);
}

// ---------------- pexp ----------------
#define PE_SMEM 101376
__global__ void __launch_bounds__(256) pexp_tc() {
    extern __shared__ char sm[];
    uint32_t raw = smem_u32(sm);
    uint32_t SAH = raw, SAL = raw + 16384, SBH = raw + 32768, SBL = raw + 49152;
    float* stg   = (float*)(sm + 32768);
    float* rsum  = (float*)(sm + 100352);
    float* rmaxS = (float*)(sm + 100864);

    int tid = threadIdx.x, lane = tid & 31, wid = tid >> 5;
    int wm = wid >> 2, wn = wid & 3;
    int m0 = blockIdx.y * 128, nc0 = blockIdx.x * 1280;

    #pragma unroll
    for (int q = 0; q < 8; q++) {
        int id = tid + 256 * q;
        int hf = id >> 10, u = id & 1023;
        int row = u >> 3, c16 = u & 7;
        const __half* src = hf ? g_El : g_Eh;
        uint4 v = *(const uint4*)(src + (size_t)(m0 + row) * 64 + c16 * 8);
        *(uint4*)(sm + (hf ? 16384 : 0) + row * 128 + ((c16 ^ (row & 7)) * 16)) = v;
    }
    if (tid < 128) { rsum[tid] = 0.0f; rmaxS[tid] = g_rowmax[m0 + tid]; }
    __syncthreads();

    int hb = lane >> 4, bbit = (lane >> 3) & 1;
    uint32_t a_off[4], a7[4], b_off[4], b7[4];
    #pragma unroll
    for (int mf = 0; mf < 4; mf++) {
        int ar = wm * 64 + mf * 16 + (lane & 15);
        a_off[mf] = (uint32_t)(ar * 128); a7[mf] = (uint32_t)(ar & 7);
    }
    #pragma unroll
    for (int nf = 0; nf < 4; nf++) {
        int br = wn * 32 + nf * 8 + (lane & 7);
        b_off[nf] = (uint32_t)(br * 128); b7[nf] = (uint32_t)(br & 7);
    }

    for (int sub = 0; sub < 10; sub++) {
        int n0 = nc0 + sub * 128;
        #pragma unroll
        for (int q = 0; q < 8; q++) {
            int id = tid + 256 * q;
            int hf = id >> 10, u = id & 1023;
            int row = u >> 3, c16 = u & 7;
            const __half* src = hf ? g_El : g_Eh;
            uint4 v = *(const uint4*)(src + (size_t)(n0 + row) * 64 + c16 * 8);
            *(uint4*)(sm + (hf ? 49152 : 32768) + row * 128 + ((c16 ^ (row & 7)) * 16)) = v;
        }
        __syncthreads();

        float acc[4][4][4];
        #pragma unroll
        for (int mf = 0; mf < 4; mf++)
            #pragma unroll
            for (int nf = 0; nf < 4; nf++)
                #pragma unroll
                for (int e = 0; e < 4; e++) acc[mf][nf][e] = 0.0f;
        #pragma unroll
        for (int ks = 0; ks < 4; ks++) {
            uint32_t ah[4][4], al[4][4], bh[4][2], bl[4][2];
            uint32_t ca = (uint32_t)(ks * 2 + hb), cb = (uint32_t)(ks * 2 + bbit);
            #pragma unroll
            for (int mf = 0; mf < 4; mf++) {
                uint32_t xo = a_off[mf] + ((ca ^ a7[mf]) << 4);
                ldsm4(ah[mf], SAH + xo);
                ldsm4(al[mf], SAL + xo);
            }
            #pragma unroll
            for (int nf = 0; nf < 4; nf++) {
                uint32_t xo = b_off[nf] + ((cb ^ b7[nf]) << 4);
                ldsm2(bh[nf], SBH + xo);
                ldsm2(bl[nf], SBL + xo);
            }
            #pragma unroll
            for (int mf = 0; mf < 4; mf++)
                #pragma unroll
                for (int nf = 0; nf < 4; nf++) {
                    mma_h(acc[mf][nf], ah[mf], bh[nf]);
                    mma_h(acc[mf][nf], ah[mf], bl[nf]);
                    mma_h(acc[mf][nf], al[mf], bh[nf]);
                }
        }
        __syncthreads();

        int g = lane >> 2, t4 = lane & 3;
        #pragma unroll
        for (int mf = 0; mf < 4; mf++) {
            int r1 = wm * 64 + mf * 16 + g, r2 = r1 + 8;
            float mx1 = rmaxS[r1], mx2 = rmaxS[r2];
            #pragma unroll
            for (int nf = 0; nf < 4; nf++) {
                int c = wn * 32 + nf * 8 + t4 * 2;
                stg[r1 * 132 + c]     = __expf(fmaxf(acc[mf][nf][0], 0.0f) - mx1);
                stg[r1 * 132 + c + 1] = __expf(fmaxf(acc[mf][nf][1], 0.0f) - mx1);
                stg[r2 * 132 + c]     = __expf(fmaxf(acc[mf][nf][2], 0.0f) - mx2);
                stg[r2 * 132 + c + 1] = __expf(fmaxf(acc[mf][nf][3], 0.0f) - mx2);
            }
        }
        __syncthreads();

        if (tid < 128) {
            float s = 0.0f;
            #pragma unroll 8
            for (int c = 0; c < 128; c++) s += stg[tid * 132 + c];
            rsum[tid] += s;
        }
        #pragma unroll
        for (int q = 0; q < 8; q++) {
            int id = tid + 256 * q;
            int row = id >> 4, cu = id & 15;
            uint32_t wh[4];
            #pragma unroll
            for (int p = 0; p < 4; p++)
                wh[p] = pack2h(stg[row * 132 + cu * 8 + 2 * p],
                               stg[row * 132 + cu * 8 + 2 * p + 1]);
            *(uint4*)(g_Ph + (size_t)(m0 + row) * MP + n0 + cu * 8) =
                make_uint4(wh[0], wh[1], wh[2], wh[3]);
        }
        __syncthreads();
    }
    if (tid < 128) g_rsp[blockIdx.x][m0 + tid] = rsum[tid];
}

// ---------------- HMMA GEMM: split-k dual warp groups, 512 threads ----------------
#define MT 160
#define JT 128
#define ABYTES 20480
#define BBYTES 16384
#define GSTG   (ABYTES + BBYTES)          // 36864 per stage
#define SMEM_BYTES (1024 + 6 * GSTG)      // 222208
#define SST 132

__global__ void __launch_bounds__(512, 1) tc_gemm(int which) {
    extern __shared__ char dsm[];
    uint32_t raw = smem_u32(dsm);
    uint32_t sb = (raw + 1023u) & ~1023u;

    int tid = threadIdx.x, lane = tid & 31, wid = tid >> 5;
    int grp = wid >> 3;                  // 0 or 1: chunk parity group
    int wg  = wid & 7;
    int wm = wg >> 2, wn = wg & 3;
    int gtid = tid & 255;                // thread index within group
    int m0 = blockIdx.y * MT, j0 = blockIdx.x * JT;

    const __half* __restrict__ BT = which ? g_y1T_h : g_xT_h;

    uint32_t sA[5], sB[4];
    size_t gA[5], gB[4];
    #pragma unroll
    for (int q = 0; q < 5; q++) {
        int u = gtid + 256 * q;
        int row = u >> 3, c16 = u & 7;
        sA[q] = (uint32_t)(row * 128 + ((c16 ^ (row & 7)) * 16));
        gA[q] = (size_t)(m0 + row) * MP + c16 * 8;
    }
    #pragma unroll
    for (int q = 0; q < 4; q++) {
        int u = gtid + 256 * q;
        int row = u >> 3, c16 = u & 7;
        sB[q] = (uint32_t)(row * 128 + ((c16 ^ (row & 7)) * 16));
        gB[q] = (size_t)(j0 + row) * MP + c16 * 8;
    }

    // group g handles chunks t = 2l+g, l = 0..39; stage = grp*3 + l%3
    auto issueg = [&](int l) {
        uint32_t base = sb + (uint32_t)(grp * 3 + l % 3) * GSTG;
        size_t ko = (size_t)(2 * l + grp) * 64;
        #pragma unroll
        for (int q = 0; q < 5; q++) cpa16(base + sA[q], g_Ph + gA[q] + ko);
        #pragma unroll
        for (int q = 0; q < 4; q++) cpa16(base + ABYTES + sB[q], BT + gB[q] + ko);
        asm volatile("cp.async.commit_group;" ::: "memory");
    };

    uint32_t a_off[5], a7[5], b_off[4], b7[4];
    int hb = lane >> 4, bbit = (lane >> 3) & 1;
    #pragma unroll
    for (int mf = 0; mf < 5; mf++) {
        int ar = wm * 80 + mf * 16 + (lane & 15);
        a_off[mf] = (uint32_t)(ar * 128); a7[mf] = (uint32_t)(ar & 7);
    }
    #pragma unroll
    for (int nf = 0; nf < 4; nf++) {
        int br = wn * 32 + nf * 8 + (lane & 7);
        b_off[nf] = (uint32_t)(br * 128); b7[nf] = (uint32_t)(br & 7);
    }

    float acc[5][4][4];
    #pragma unroll
    for (int mf = 0; mf < 5; mf++)
        #pragma unroll
        for (int nf = 0; nf < 4; nf++)
            #pragma unroll
            for (int e = 0; e < 4; e++) acc[mf][nf][e] = 0.0f;

    issueg(0); issueg(1);

    uint32_t af[2][5][4], bfr[2][4][2];
    for (int l = 0; l < 40; l++) {
        if (l < 39) asm volatile("cp.async.wait_group 1;" ::: "memory");
        else        asm volatile("cp.async.wait_group 0;" ::: "memory");
        asm volatile("bar.sync %0, %1;" :: "r"(grp + 1), "r"(256) : "memory");
        if (l + 2 < 40) issueg(l + 2);

        uint32_t Abuf = sb + (uint32_t)(grp * 3 + l % 3) * GSTG;
        uint32_t Bbuf = Abuf + ABYTES;

        {
            uint32_t ca = (uint32_t)hb, cb = (uint32_t)bbit;
            #pragma unroll
            for (int mf = 0; mf < 5; mf++) ldsm4(af[0][mf], Abuf + a_off[mf] + ((ca ^ a7[mf]) << 4));
            #pragma unroll
            for (int nf = 0; nf < 4; nf++) ldsm2(bfr[0][nf], Bbuf + b_off[nf] + ((cb ^ b7[nf]) << 4));
        }
        #pragma unroll
        for (int ks = 0; ks < 4; ks++) {
            int cur = ks & 1, nxt = cur ^ 1;
            if (ks < 3) {
                uint32_t ca = (uint32_t)((ks + 1) * 2 + hb), cb = (uint32_t)((ks + 1) * 2 + bbit);
                #pragma unroll
                for (int mf = 0; mf < 5; mf++) ldsm4(af[nxt][mf], Abuf + a_off[mf] + ((ca ^ a7[mf]) << 4));
                #pragma unroll
                for (int nf = 0; nf < 4; nf++) ldsm2(bfr[nxt][nf], Bbuf + b_off[nf] + ((cb ^ b7[nf]) << 4));
            }
            #pragma unroll
            for (int mf = 0; mf < 5; mf++)
                #pragma unroll
                for (int nf = 0; nf < 4; nf++)
                    mma_h(acc[mf][nf], af[cur][mf], bfr[cur][nf]);
        }
    }
    __syncthreads();   // both groups done; all cp.async drained (wait_group 0 in last iter)

    // ---- cross-group reduction + scale + writeout ----
    float* st = (float*)(dsm + (sb - raw));
    int g = lane >> 2, t4 = lane & 3;

    if (grp == 1) {
        #pragma unroll
        for (int mf = 0; mf < 5; mf++) {
            int r0 = wm * 80 + mf * 16 + g;
            #pragma unroll
            for (int nf = 0; nf < 4; nf++) {
                int c0 = wn * 32 + nf * 8 + t4 * 2;
                st[r0 * SST + c0]           = acc[mf][nf][0];
                st[r0 * SST + c0 + 1]       = acc[mf][nf][1];
                st[(r0 + 8) * SST + c0]     = acc[mf][nf][2];
                st[(r0 + 8) * SST + c0 + 1] = acc[mf][nf][3];
            }
        }
    }
    __syncthreads();
    if (grp == 0) {
        #pragma unroll
        for (int mf = 0; mf < 5; mf++) {
            int r0 = wm * 80 + mf * 16 + g;
            int ma = m0 + r0, mb = ma + 8;
            float al0 = 0.0f, al1 = 0.0f;
            if (ma < Nn) al0 = 1.0f / (g_rsp[0][ma] + g_rsp[1][ma] + g_rsp[2][ma] + g_rsp[3][ma]);
            if (mb < Nn) al1 = 1.0f / (g_rsp[0][mb] + g_rsp[1][mb] + g_rsp[2][mb] + g_rsp[3][mb]);
            #pragma unroll
            for (int nf = 0; nf < 4; nf++) {
                int c0 = wn * 32 + nf * 8 + t4 * 2;
                st[r0 * SST + c0]           = (acc[mf][nf][0] + st[r0 * SST + c0]) * al0;
                st[r0 * SST + c0 + 1]       = (acc[mf][nf][1] + st[r0 * SST + c0 + 1]) * al0;
                st[(r0 + 8) * SST + c0]     = (acc[mf][nf][2] + st[(r0 + 8) * SST + c0]) * al1;
                st[(r0 + 8) * SST + c0 + 1] = (acc[mf][nf][3] + st[(r0 + 8) * SST + c0 + 1]) * al1;
            }
        }
    }
    __syncthreads();

    float* __restrict__ Y = which ? g_y2 : g_y1;
    for (int u = tid; u < MT * 32; u += 512) {
        int r = u >> 5, ch = u & 31;
        int m = m0 + r;
        if (m < Nn) {
            float4 v = {st[r * SST + ch * 4],     st[r * SST + ch * 4 + 1],
                        st[r * SST + ch * 4 + 2], st[r * SST + ch * 4 + 3]};
            *(float4*)&Y[(size_t)m * 512 + j0 + ch * 4] = v;
        }
    }
    if (which == 0) {
        for (int u = tid; u < JT * 20; u += 512) {
            int j = u / 20, mm = u % 20;
            uint32_t w[4];
            #pragma unroll
            for (int p = 0; p < 4; p++)
                w[p] = pack2h(st[(mm * 8 + 2 * p) * SST + j],
                              st[(mm * 8 + 2 * p + 1) * SST + j]);
            *(uint4*)&g_y1T_h[(size_t)(j0 + j) * MP + m0 + mm * 8] =
                make_uint4(w[0], w[1], w[2], w[3]);
        }
    }
}

// ---------------- pool_tc ----------------
__global__ void __launch_bounds__(256) pool_tc() {
    __shared__ __align__(16) char sm[49152];
    uint32_t raw = smem_u32(sm);
    uint32_t SAH = raw, SAL = raw + 16384, SBH = raw + 32768;
    int tid = threadIdx.x, lane = tid & 31, wid = tid >> 5;
    int wm = wid >> 2, wn = wid & 3;
    int m0 = blockIdx.y * 128, j0 = blockIdx.x * 128;

    #pragma unroll
    for (int q = 0; q < 4; q++) {
        int u = tid + 256 * q;
        int row = u >> 3, c16 = u & 7;
        uint32_t so = (uint32_t)(row * 128 + ((c16 ^ (row & 7)) * 16));
        *(uint4*)(sm + so)          = *(const uint4*)(g_Eh + (size_t)(m0 + row) * 64 + c16 * 8);
        *(uint4*)(sm + 16384 + so)  = *(const uint4*)(g_El + (size_t)(m0 + row) * 64 + c16 * 8);
        *(uint4*)(sm + 32768 + so)  = *(const uint4*)(g_WT + (size_t)(j0 + row) * 64 + c16 * 8);
    }
    __syncthreads();

    int hb = lane >> 4, bbit = (lane >> 3) & 1;
    uint32_t a_off[4], a7[4], b_off[4], b7[4];
    #pragma unroll
    for (int mf = 0; mf < 4; mf++) {
        int ar = wm * 64 + mf * 16 + (lane & 15);
        a_off[mf] = (uint32_t)(ar * 128); a7[mf] = (uint32_t)(ar & 7);
    }
    #pragma unroll
    for (int nf = 0; nf < 4; nf++) {
        int br = wn * 32 + nf * 8 + (lane & 7);
        b_off[nf] = (uint32_t)(br * 128); b7[nf] = (uint32_t)(br & 7);
    }

    float acc[4][4][4];
    #pragma unroll
    for (int mf = 0; mf < 4; mf++)
        #pragma unroll
        for (int nf = 0; nf < 4; nf++)
            #pragma unroll
            for (int e = 0; e < 4; e++) acc[mf][nf][e] = 0.0f;

    #pragma unroll
    for (int ks = 0; ks < 4; ks++) {
        uint32_t ah[4][4], al[4][4], bh[4][2];
        uint32_t ca = (uint32_t)(ks * 2 + hb), cb = (uint32_t)(ks * 2 + bbit);
        #pragma unroll
        for (int mf = 0; mf < 4; mf++) {
            uint32_t xo = a_off[mf] + ((ca ^ a7[mf]) << 4);
            ldsm4(ah[mf], SAH + xo);
            ldsm4(al[mf], SAL + xo);
        }
        #pragma unroll
        for (int nf = 0; nf < 4; nf++) ldsm2(bh[nf], SBH + b_off[nf] + ((cb ^ b7[nf]) << 4));
        #pragma unroll
        for (int mf = 0; mf < 4; mf++)
            #pragma unroll
            for (int nf = 0; nf < 4; nf++) {
                mma_h(acc[mf][nf], ah[mf], bh[nf]);
                mma_h(acc[mf][nf], al[mf], bh[nf]);
            }
    }

    int g = lane >> 2, t4 = lane & 3;
    #pragma unroll
    for (int mf = 0; mf < 4; mf++) {
        int r1 = m0 + wm * 64 + mf * 16 + g;
        #pragma unroll
        for (int nf = 0; nf < 4; nf++) {
            int c = j0 + wn * 32 + nf * 8 + t4 * 2;
            *(uint32_t*)&g_W16[(size_t)r1 * 3584 + c] = pack2h(acc[mf][nf][0], acc[mf][nf][1]);
            *(uint32_t*)&g_W16[(size_t)(r1 + 8) * 3584 + c] = pack2h(acc[mf][nf][2], acc[mf][nf][3]);
        }
    }
}

// ---------------- xwagg ----------------
__global__ void xwagg_kernel(const float* __restrict__ xw, const float* __restrict__ T) {
    int idx = blockIdx.x * 256 + threadIdx.x;
    if (idx >= Nn * Bb * 16) return;
    int n = idx >> 8, r = idx & 255, b = r >> 4, i = r & 15;
    float s = 0.0f;
    #pragma unroll
    for (int t = 0; t < 12; t++)
        s = fmaf(__ldg(&T[t]), xw[(((size_t)b * 12 + t) * Nn + n) * 16 + i], s);
    g_xwagg[idx] = s;
}

// ---------------- fused epilogue ----------------
__global__ void __launch_bounds__(128) final_kernel(const float* __restrict__ x,
                                                    const float* __restrict__ emb,
                                                    const float* __restrict__ bpool,
                                                    const float* __restrict__ ln1w,
                                                    const float* __restrict__ ln1b,
                                                    const float* __restrict__ ln2w,
                                                    const float* __restrict__ ln2b,
                                                    float* __restrict__ out) {
    int n = blockIdx.x;
    int tid = threadIdx.x;
    __shared__ float sW[3072];
    __shared__ float sww[512];
    __shared__ float sx[3][512];
    __shared__ float sxa[256];
    __shared__ float sg[512];
    __shared__ float sw2[512];
    __shared__ float semb[64];
    __shared__ float sbias[64];
    __shared__ float smu[16], srs[16], smu2[16], srs2[16];

    for (int u = tid; u < 448; u += 128) {
        uint4 v = *(const uint4*)&g_W16[(size_t)n * 3584 + u * 8];
        const __half* h = (const __half*)&v;
        int base = u * 8;
        if (base < 3072) {
            #pragma unroll
            for (int p = 0; p < 8; p++) sW[base + p] = __half2float(h[p]);
        } else {
            #pragma unroll
            for (int p = 0; p < 8; p++) sww[base - 3072 + p] = __half2float(h[p]);
        }
    }
    {
        int b = tid >> 3, i4 = (tid & 7) * 4;
        *(float4*)&sx[0][tid * 4] = *(const float4*)&x[((size_t)b * Nn + n) * 32 + i4];
    }
    *(float4*)&sx[1][tid * 4] = *(const float4*)&g_y1[(size_t)n * 512 + tid * 4];
    *(float4*)&sx[2][tid * 4] = *(const float4*)&g_y2[(size_t)n * 512 + tid * 4];
    if (tid < 64) {
        *(float4*)&sxa[tid * 4] = *(const float4*)&g_xwagg[(size_t)n * 256 + tid * 4];
        semb[tid] = emb[(size_t)n * 64 + tid];
    }
    __syncthreads();

    #pragma unroll
    for (int q = 0; q < 4; q++) {
        int s = tid + 128 * q;
        int b = s >> 5, o = s & 31;
        float a = 0.0f;
        #pragma unroll
        for (int k = 0; k < 3; k++)
            #pragma unroll
            for (int i = 0; i < 32; i++)
                a = fmaf(sx[k][b * 32 + i], sW[k * 1024 + i * 32 + o], a);
        sg[s] = a;
        float w = 0.0f;
        #pragma unroll
        for (int i = 0; i < 16; i++)
            w = fmaf(sxa[b * 16 + i], sww[i * 32 + o], w);
        sw2[s] = w;
    }
    if (tid < 64) {
        float bsum = 0.0f;
        #pragma unroll
        for (int d = 0; d < 64; d++)
            bsum = fmaf(semb[d], __ldg(&bpool[d * 64 + tid]), bsum);
        sbias[tid] = bsum;
    }
    __syncthreads();

    if (tid < 16) {
        float s1 = 0, q1 = 0, s2 = 0, q2 = 0;
        #pragma unroll
        for (int o = 0; o < 32; o++) {
            float v = sg[tid * 32 + o];
            s1 += v; q1 = fmaf(v, v, q1);
            float u = sw2[tid * 32 + o];
            s2 += u; q2 = fmaf(u, u, q2);
        }
        float mu1 = s1 * (1.0f / 32.0f), mu2 = s2 * (1.0f / 32.0f);
        smu[tid] = mu1;
        srs[tid] = rsqrtf(fmaxf(q1 * (1.0f / 32.0f) - mu1 * mu1, 0.0f) + 1e-5f);
        smu2[tid] = mu2;
        srs2[tid] = rsqrtf(fmaxf(q2 * (1.0f / 32.0f) - mu2 * mu2, 0.0f) + 1e-5f);
    }
    __syncthreads();

    #pragma unroll
    for (int q = 0; q < 8; q++) {
        int s = tid + 128 * q;
        int b = s >> 6, h = s & 63;
        float v;
        if (h < 32)
            v = (sg[b * 32 + h] - smu[b]) * srs[b] * __ldg(&ln1w[h]) + __ldg(&ln1b[h]);
        else
            v = (sw2[b * 32 + h - 32] - smu2[b]) * srs2[b] * __ldg(&ln2w[h - 32]) + __ldg(&ln2b[h - 32]);
        out[((size_t)b * Nn + n) * 64 + h] = v + sbias[h];
    }
}

extern "C" void kernel_launch(void* const* d_in, const int* in_sizes, int n_in,
                              void* d_out, int out_size) {
    const float* x    = (const float*)d_in[0];
    const float* xw   = (const float*)d_in[1];
    const float* emb  = (const float*)d_in[2];
    const float* wp   = (const float*)d_in[3];
    const float* wwin = (const float*)d_in[4];
    const float* bp   = (const float*)d_in[5];
    const float* T    = (const float*)d_in[6];
    const float* l1w  = (const float*)d_in[7];
    const float* l1b  = (const float*)d_in[8];
    const float* l2w  = (const float*)d_in[9];
    const float* l2b  = (const float*)d_in[10];
    float* out = (float*)d_out;

    cudaFuncSetAttribute(pexp_tc, cudaFuncAttributeMaxDynamicSharedMemorySize, PE_SMEM);
    cudaFuncSetAttribute(tc_gemm, cudaFuncAttributeMaxDynamicSharedMemorySize, SMEM_BYTES);

    prep_kernel<<<666, 256>>>(x, emb, wp, wwin);             // 0
    rowmax_tc<<<dim3(2, 40), 256>>>();                       // 1
    pexp_tc<<<dim3(4, 40), 256, PE_SMEM>>>();                // 2
    tc_gemm<<<dim3(4, 32), 512, SMEM_BYTES>>>(0);            // 3  <- profiled slot
    tc_gemm<<<dim3(4, 32), 512, SMEM_BYTES>>>(1);            // 4
    pool_tc<<<dim3(28, 40), 256>>>();                        // 5
    xwagg_kernel<<<(Nn * Bb * 16 + 255) / 256, 256>>>(xw, T);// 6
    final_kernel<<<Nn, 128>>>(x, emb, bp, l1w, l1b, l2w, l2b, out); // 7
}